// round 12
// baseline (speedup 1.0000x reference)
#include <cuda_runtime.h>
#include <cuda_fp16.h>
#include <math.h>
#include <stdint.h>

#define SD 2048
#define ED 1024
#define HD 16
#define DD 64
#define BD 2
#define BH (BD*HD)     /* 32 */
#define ROWS (BD*SD)   /* 4096 */
#define BHS (BH*SD)    /* 65536 */

#define C1 11.5415603f   /* 8*log2(e) */
#define C2 23.0831206f   /* 16*log2(e) */

#define N4X (ROWS * ED / 4)   /* 1048576 */
#define N4W (ED * ED / 4)     /*  262144 */

// ---------------- scratch ----------------
__device__ __half g_xh[(size_t)ROWS * ED];
__device__ __half g_xl[(size_t)ROWS * ED];
__device__ __half g_wqh[(size_t)ED * ED];
__device__ __half g_wql[(size_t)ED * ED];
__device__ __half g_wkh[(size_t)ED * ED];
__device__ __half g_wkl[(size_t)ED * ED];
__device__ __half g_wvh[(size_t)ED * ED];
__device__ __half g_woh[(size_t)ED * ED];
__device__ __half g_Qh[(size_t)BHS * DD];
__device__ __half g_Ql[(size_t)BHS * DD];
__device__ __half g_Kh[(size_t)BHS * DD];
__device__ __half g_Kl[(size_t)BHS * DD];
__device__ __half g_Vh[(size_t)BHS * DD];
__device__ __half g_qMh[(size_t)BHS * DD];
__device__ __half g_qMl[(size_t)BHS * DD];
__device__ float  g_qMq[BHS];
__device__ float  g_kMk[BHS];
__device__ float  g_rowm[BHS];
__device__ float  g_rowl[BHS];
__device__ float  g_blkm[(size_t)BHS * 32];      /* per-64-col block max */
__device__ __half g_P[(size_t)BH * SD * SD];     /* 268 MB: unnormalized probs fp16 */
__device__ __half g_ctxh[(size_t)ROWS * ED];
__device__ __half g_ctxl[(size_t)ROWS * ED];
__device__ float  g_tmp[(size_t)ROWS * ED];

// ---------------- helpers ----------------
__device__ __forceinline__ float ex2(float x) {
    float y; asm("ex2.approx.f32 %0, %1;" : "=f"(y) : "f"(x)); return y;
}

__device__ __forceinline__ void mma16816(float (&c)[4],
    uint32_t a0, uint32_t a1, uint32_t a2, uint32_t a3, uint32_t b0, uint32_t b1)
{
    asm volatile(
        "mma.sync.aligned.m16n8k16.row.col.f32.f16.f16.f32 "
        "{%0,%1,%2,%3}, {%4,%5,%6,%7}, {%8,%9}, {%0,%1,%2,%3};"
        : "+f"(c[0]), "+f"(c[1]), "+f"(c[2]), "+f"(c[3])
        : "r"(a0), "r"(a1), "r"(a2), "r"(a3), "r"(b0), "r"(b1));
}

__device__ __forceinline__ void ldsm4(uint32_t& r0, uint32_t& r1, uint32_t& r2, uint32_t& r3,
                                      uint32_t addr)
{
    asm volatile("ldmatrix.sync.aligned.m8n8.x4.shared.b16 {%0,%1,%2,%3}, [%4];"
        : "=r"(r0), "=r"(r1), "=r"(r2), "=r"(r3) : "r"(addr));
}

__device__ __forceinline__ uint32_t ld_u32(const __half* p) {
    return *reinterpret_cast<const uint32_t*>(p);
}

__device__ __forceinline__ void split_st(__half* ph, __half* pl, float x, float y) {
    __half hx = __float2half_rn(x), hy = __float2half_rn(y);
    *reinterpret_cast<__half2*>(ph) = __halves2half2(hx, hy);
    __half lx = __float2half_rn(x - __half2float(hx));
    __half ly = __float2half_rn(y - __half2float(hy));
    *reinterpret_cast<__half2*>(pl) = __halves2half2(lx, ly);
}

// ---------------- fused converter ----------------
__global__ __launch_bounds__(256) void prep_kernel(
    const float* __restrict__ x,
    const float* __restrict__ Wq, const float* __restrict__ Wk,
    const float* __restrict__ Wv, const float* __restrict__ Wo)
{
    int i = blockIdx.x * 256 + threadIdx.x;
    if (i < N4X) {
        float4 v = ((const float4*)x)[i];
        split_st(g_xh + 4 * (size_t)i,     g_xl + 4 * (size_t)i,     v.x, v.y);
        split_st(g_xh + 4 * (size_t)i + 2, g_xl + 4 * (size_t)i + 2, v.z, v.w);
        return;
    }
    int j = i - N4X;
    int w = j / N4W, o = j % N4W;
    if (w == 0) {
        float4 v = ((const float4*)Wq)[o];
        split_st(g_wqh + 4 * (size_t)o,     g_wql + 4 * (size_t)o,     v.x, v.y);
        split_st(g_wqh + 4 * (size_t)o + 2, g_wql + 4 * (size_t)o + 2, v.z, v.w);
    } else if (w == 1) {
        float4 v = ((const float4*)Wk)[o];
        split_st(g_wkh + 4 * (size_t)o,     g_wkl + 4 * (size_t)o,     v.x, v.y);
        split_st(g_wkh + 4 * (size_t)o + 2, g_wkl + 4 * (size_t)o + 2, v.z, v.w);
    } else if (w == 2) {
        float4 v = ((const float4*)Wv)[o];
        __half2* d = (__half2*)(g_wvh + 4 * (size_t)o);
        d[0] = __floats2half2_rn(v.x, v.y);
        d[1] = __floats2half2_rn(v.z, v.w);
    } else {
        float4 v = ((const float4*)Wo)[o];
        __half2* d = (__half2*)(g_woh + 4 * (size_t)o);
        d[0] = __floats2half2_rn(v.x, v.y);
        d[1] = __floats2half2_rn(v.z, v.w);
    }
}

// ---------------- 128x128 HGEMM core (unchanged) ----------------
template <int MODE, int NSPLIT>
__device__ __forceinline__ void hgemm_core(
    char* smem,
    const __half* __restrict__ Ahg, const __half* __restrict__ Alg,
    const __half* __restrict__ Bhg, const __half* __restrict__ Blg,
    float* __restrict__ C, __half* __restrict__ Ch, __half* __restrict__ Cl,
    const float* __restrict__ bias, const float* __restrict__ resid)
{
    __half (*Ah)[40] = (__half(*)[40])smem;
    __half (*Bh)[40] = Ah + 128;
    __half (*Al)[40] = Ah + 256;
    __half (*Bl)[40] = Ah + 384;
    const int t = threadIdx.x;
    const int wid = t >> 5, lane = t & 31;
    const int g = lane >> 2, tg = lane & 3;
    const int wr = wid >> 1, wc = wid & 1;
    const int row0 = blockIdx.y * 128, col0 = blockIdx.x * 128;
    const int lr = t >> 1, lq = (t & 1) * 16;
    const __half* Aph = Ahg + (size_t)(row0 + lr) * ED + lq;
    const __half* Apl = (NSPLIT >= 2) ? Alg + (size_t)(row0 + lr) * ED + lq : nullptr;
    const __half* Bph = Bhg + (size_t)(col0 + lr) * ED + lq;
    const __half* Bpl = (NSPLIT >= 3) ? Blg + (size_t)(col0 + lr) * ED + lq : nullptr;

    float acc[2][8][4];
#pragma unroll
    for (int mt = 0; mt < 2; mt++)
#pragma unroll
        for (int nt = 0; nt < 8; nt++)
#pragma unroll
            for (int j = 0; j < 4; j++) acc[mt][nt][j] = 0.f;

    uint4 va0 = *(const uint4*)(Aph),  va1 = *(const uint4*)(Aph + 8);
    uint4 vb0 = *(const uint4*)(Bph),  vb1 = *(const uint4*)(Bph + 8);
    uint4 vl0, vl1, vm0, vm1;
    if (NSPLIT >= 2) { vl0 = *(const uint4*)(Apl); vl1 = *(const uint4*)(Apl + 8); }
    if (NSPLIT >= 3) { vm0 = *(const uint4*)(Bpl); vm1 = *(const uint4*)(Bpl + 8); }

    for (int k0 = 0; k0 < ED; k0 += 32) {
        *(uint4*)&Ah[lr][lq] = va0; *(uint4*)&Ah[lr][lq + 8] = va1;
        *(uint4*)&Bh[lr][lq] = vb0; *(uint4*)&Bh[lr][lq + 8] = vb1;
        if (NSPLIT >= 2) { *(uint4*)&Al[lr][lq] = vl0; *(uint4*)&Al[lr][lq + 8] = vl1; }
        if (NSPLIT >= 3) { *(uint4*)&Bl[lr][lq] = vm0; *(uint4*)&Bl[lr][lq + 8] = vm1; }
        __syncthreads();
        if (k0 + 32 < ED) {
            va0 = *(const uint4*)(Aph + k0 + 32); va1 = *(const uint4*)(Aph + k0 + 40);
            vb0 = *(const uint4*)(Bph + k0 + 32); vb1 = *(const uint4*)(Bph + k0 + 40);
            if (NSPLIT >= 2) { vl0 = *(const uint4*)(Apl + k0 + 32); vl1 = *(const uint4*)(Apl + k0 + 40); }
            if (NSPLIT >= 3) { vm0 = *(const uint4*)(Bpl + k0 + 32); vm1 = *(const uint4*)(Bpl + k0 + 40); }
        }
#pragma unroll
        for (int ks = 0; ks < 2; ks++) {
            const int kb = ks * 16;
            uint32_t ahi[2][4], alo[2][4];
#pragma unroll
            for (int mt = 0; mt < 2; mt++) {
                const int r0 = wr * 32 + mt * 16;
                ahi[mt][0] = ld_u32(&Ah[r0 + g][kb + 2 * tg]);
                ahi[mt][1] = ld_u32(&Ah[r0 + g + 8][kb + 2 * tg]);
                ahi[mt][2] = ld_u32(&Ah[r0 + g][kb + 2 * tg + 8]);
                ahi[mt][3] = ld_u32(&Ah[r0 + g + 8][kb + 2 * tg + 8]);
                if (NSPLIT >= 2) {
                    alo[mt][0] = ld_u32(&Al[r0 + g][kb + 2 * tg]);
                    alo[mt][1] = ld_u32(&Al[r0 + g + 8][kb + 2 * tg]);
                    alo[mt][2] = ld_u32(&Al[r0 + g][kb + 2 * tg + 8]);
                    alo[mt][3] = ld_u32(&Al[r0 + g + 8][kb + 2 * tg + 8]);
                }
            }
#pragma unroll
            for (int nt = 0; nt < 8; nt++) {
                const int nr = wc * 64 + nt * 8 + g;
                uint32_t bh0 = ld_u32(&Bh[nr][kb + 2 * tg]);
                uint32_t bh1 = ld_u32(&Bh[nr][kb + 2 * tg + 8]);
#pragma unroll
                for (int mt = 0; mt < 2; mt++) {
                    mma16816(acc[mt][nt], ahi[mt][0], ahi[mt][1], ahi[mt][2], ahi[mt][3], bh0, bh1);
                    if (NSPLIT >= 3) {
                        uint32_t bl0 = ld_u32(&Bl[nr][kb + 2 * tg]);
                        uint32_t bl1 = ld_u32(&Bl[nr][kb + 2 * tg + 8]);
                        mma16816(acc[mt][nt], ahi[mt][0], ahi[mt][1], ahi[mt][2], ahi[mt][3], bl0, bl1);
                    }
                    if (NSPLIT >= 2)
                        mma16816(acc[mt][nt], alo[mt][0], alo[mt][1], alo[mt][2], alo[mt][3], bh0, bh1);
                }
            }
        }
        __syncthreads();
    }

#pragma unroll
    for (int mt = 0; mt < 2; mt++) {
        const int rA = row0 + wr * 32 + mt * 16 + g;
        const int rB = rA + 8;
#pragma unroll
        for (int nt = 0; nt < 8; nt++) {
            const int c = col0 + wc * 64 + nt * 8 + 2 * tg;
            const float b0 = bias[c], b1 = bias[c + 1];
            float v00 = acc[mt][nt][0] + b0, v01 = acc[mt][nt][1] + b1;
            float v10 = acc[mt][nt][2] + b0, v11 = acc[mt][nt][3] + b1;
            if (MODE == 3) {
                size_t iA = (size_t)rA * ED + c;
                size_t iB = (size_t)rB * ED + c;
                float2 r0 = *(const float2*)&resid[iA];
                float2 r1 = *(const float2*)&resid[iB];
                *(float2*)&C[iA] = make_float2(v00 + r0.x, v01 + r0.y);
                *(float2*)&C[iB] = make_float2(v10 + r1.x, v11 + r1.y);
            } else {
                const int h_ = c >> 6, d_ = c & 63;
                size_t iA = (((size_t)(rA >> 11) * HD + h_) * SD + (rA & (SD - 1))) * DD + d_;
                size_t iB = (((size_t)(rB >> 11) * HD + h_) * SD + (rB & (SD - 1))) * DD + d_;
                if (MODE == 4) {
                    split_st(&Ch[iA], &Cl[iA], v00, v01);
                    split_st(&Ch[iB], &Cl[iB], v10, v11);
                }
                if (MODE == 2) {
                    *(__half2*)&Ch[iA] = __floats2half2_rn(v00, v01);
                    *(__half2*)&Ch[iB] = __floats2half2_rn(v10, v11);
                }
            }
        }
    }
}

__global__ __launch_bounds__(256) void hgemm_qk(
    const float* __restrict__ bq, const float* __restrict__ bk)
{
    __shared__ char smem[4 * 128 * 40 * 2];
    if (blockIdx.z == 0)
        hgemm_core<4, 3>(smem, g_xh, g_xl, g_wqh, g_wql, nullptr, g_Qh, g_Ql, bq, nullptr);
    else
        hgemm_core<4, 3>(smem, g_xh, g_xl, g_wkh, g_wkl, nullptr, g_Kh, g_Kl, bk, nullptr);
}

__global__ __launch_bounds__(256) void hgemm_v(const float* __restrict__ bv)
{
    __shared__ char smem[2 * 128 * 40 * 2];
    hgemm_core<2, 1>(smem, g_xh, nullptr, g_wvh, nullptr, nullptr, g_Vh, nullptr, bv, nullptr);
}

__global__ __launch_bounds__(256) void hgemm_o(
    const float* __restrict__ bo, const float* __restrict__ resid)
{
    __shared__ char smem[3 * 128 * 40 * 2];
    hgemm_core<3, 2>(smem, g_ctxh, g_ctxl, g_woh, nullptr, g_tmp, nullptr, nullptr, bo, resid);
}

// ---------------- qm via mma (unchanged) ----------------
#define QM_SMEM (size_t)((128 + 128 + 64 + 64) * 72 * 2)
__global__ __launch_bounds__(256) void qm_mma(const float* __restrict__ M)
{
    extern __shared__ __half qsm[];
    __half (*Qh_s)[72] = (__half(*)[72])qsm;
    __half (*Ql_s)[72] = Qh_s + 128;
    __half (*Mh_s)[72] = Qh_s + 256;
    __half (*Ml_s)[72] = Qh_s + 320;
    const int t = threadIdx.x, wid = t >> 5, lane = t & 31;
    const int g = lane >> 2, tg = lane & 3;
    const int r0 = blockIdx.x * 128;
    const bool isQ = (blockIdx.y == 0);
    const __half* Ahg = isQ ? g_Qh : g_Kh;
    const __half* Alg = isQ ? g_Ql : g_Kl;

    for (int idx = t; idx < 64 * 64; idx += 256) {
        int d = idx >> 6, e = idx & 63;
        float v = M[d * 64 + e];
        __half hv = __float2half_rn(v);
        Mh_s[e][d] = hv;
        Ml_s[e][d] = __float2half_rn(v - __half2float(hv));
    }
    for (int idx = t; idx < 128 * 8; idx += 256) {
        int r = idx >> 3, c8 = (idx & 7) * 8;
        *(uint4*)&Qh_s[r][c8] = *(const uint4*)(Ahg + (size_t)(r0 + r) * DD + c8);
        *(uint4*)&Ql_s[r][c8] = *(const uint4*)(Alg + (size_t)(r0 + r) * DD + c8);
    }
    __syncthreads();

    const int rA = wid * 16 + g, rB = rA + 8;
    float acc[8][4];
#pragma unroll
    for (int nt = 0; nt < 8; nt++)
#pragma unroll
        for (int j = 0; j < 4; j++) acc[nt][j] = 0.f;

#pragma unroll
    for (int kb = 0; kb < 64; kb += 16) {
        uint32_t ah0 = ld_u32(&Qh_s[rA][kb + 2 * tg]);
        uint32_t ah1 = ld_u32(&Qh_s[rB][kb + 2 * tg]);
        uint32_t ah2 = ld_u32(&Qh_s[rA][kb + 2 * tg + 8]);
        uint32_t ah3 = ld_u32(&Qh_s[rB][kb + 2 * tg + 8]);
        uint32_t al0 = ld_u32(&Ql_s[rA][kb + 2 * tg]);
        uint32_t al1 = ld_u32(&Ql_s[rB][kb + 2 * tg]);
        uint32_t al2 = ld_u32(&Ql_s[rA][kb + 2 * tg + 8]);
        uint32_t al3 = ld_u32(&Ql_s[rB][kb + 2 * tg + 8]);
#pragma unroll
        for (int nt = 0; nt < 8; nt++) {
            const int nr = nt * 8 + g;
            uint32_t bh0 = ld_u32(&Mh_s[nr][kb + 2 * tg]);
            uint32_t bh1 = ld_u32(&Mh_s[nr][kb + 2 * tg + 8]);
            uint32_t bl0 = ld_u32(&Ml_s[nr][kb + 2 * tg]);
            uint32_t bl1 = ld_u32(&Ml_s[nr][kb + 2 * tg + 8]);
            mma16816(acc[nt], ah0, ah1, ah2, ah3, bh0, bh1);
            mma16816(acc[nt], ah0, ah1, ah2, ah3, bl0, bl1);
            mma16816(acc[nt], al0, al1, al2, al3, bh0, bh1);
        }
    }

    float dotA = 0.f, dotB = 0.f;
#pragma unroll
    for (int nt = 0; nt < 8; nt++) {
        const int c0 = nt * 8 + 2 * tg;
        if (isQ) {
            split_st(&g_qMh[(size_t)(r0 + rA) * DD + c0], &g_qMl[(size_t)(r0 + rA) * DD + c0],
                     acc[nt][0], acc[nt][1]);
            split_st(&g_qMh[(size_t)(r0 + rB) * DD + c0], &g_qMl[(size_t)(r0 + rB) * DD + c0],
                     acc[nt][2], acc[nt][3]);
        }
        float qA0 = __half2float(Qh_s[rA][c0])     + __half2float(Ql_s[rA][c0]);
        float qA1 = __half2float(Qh_s[rA][c0 + 1]) + __half2float(Ql_s[rA][c0 + 1]);
        float qB0 = __half2float(Qh_s[rB][c0])     + __half2float(Ql_s[rB][c0]);
        float qB1 = __half2float(Qh_s[rB][c0 + 1]) + __half2float(Ql_s[rB][c0 + 1]);
        dotA = fmaf(acc[nt][0], qA0, fmaf(acc[nt][1], qA1, dotA));
        dotB = fmaf(acc[nt][2], qB0, fmaf(acc[nt][3], qB1, dotB));
    }
    dotA += __shfl_xor_sync(0xffffffffu, dotA, 1);
    dotA += __shfl_xor_sync(0xffffffffu, dotA, 2);
    dotB += __shfl_xor_sync(0xffffffffu, dotB, 1);
    dotB += __shfl_xor_sync(0xffffffffu, dotB, 2);
    if (tg == 0) {
        float* dst = isQ ? g_qMq : g_kMk;
        dst[r0 + rA] = dotA;
        dst[r0 + rB] = dotB;
    }
}

// ---------------- pass 1: 256 q-rows x 64 k-cols per iter ----------------
// warp = 32 rows x 64 cols; B (K-tile) smem redundancy amortized over 256 rows
#define SC_SMEM (size_t)((256 + 256 + 64 + 64) * 72 * 2)   /* 92160 B */
__global__ __launch_bounds__(256) void scores_mma()
{
    extern __shared__ __half smx[];
    __half (*qMh)[72] = (__half(*)[72])smx;       // [256][72]
    __half (*qMl)[72] = qMh + 256;                // [256][72]
    __half (*Kh)[72]  = qMh + 512;                // [64][72]
    __half (*Kl)[72]  = qMh + 576;                // [64][72]
    __shared__ float qq[256], kks[64];

    const int bh = blockIdx.y, q0 = blockIdx.x * 256;
    const __half* qMhb = g_qMh + (size_t)bh * SD * DD;
    const __half* qMlb = g_qMl + (size_t)bh * SD * DD;
    const __half* Khb  = g_Kh  + (size_t)bh * SD * DD;
    const __half* Klb  = g_Kl  + (size_t)bh * SD * DD;
    __half* Pb = g_P + (size_t)bh * SD * SD;
    const int t = threadIdx.x, wid = t >> 5, lane = t & 31;
    const int g = lane >> 2, tg = lane & 3;

    // ldmatrix lane addressing: A per m-tile (mt 0/1), B pairs of n-tiles
    const int aR = wid * 32 + (lane & 15), aC = (lane >> 4) * 8;
    const int bRow = ((lane >> 4) * 8) + (lane & 7);
    const int bCol = ((lane >> 3) & 1) * 8;
    const uint32_t aH0 = (uint32_t)__cvta_generic_to_shared(&qMh[aR][aC]);
    const uint32_t aH1 = (uint32_t)__cvta_generic_to_shared(&qMh[aR + 16][aC]);
    const uint32_t aL0 = (uint32_t)__cvta_generic_to_shared(&qMl[aR][aC]);
    const uint32_t aL1 = (uint32_t)__cvta_generic_to_shared(&qMl[aR + 16][aC]);
    const uint32_t bHb = (uint32_t)__cvta_generic_to_shared(&Kh[bRow][bCol]);
    const uint32_t bLb = (uint32_t)__cvta_generic_to_shared(&Kl[bRow][bCol]);
    const uint32_t PSTRIDE = 16 * 72 * 2;

    for (int idx = t; idx < 256 * 8; idx += 256) {
        int r = idx >> 3, c8 = (idx & 7) * 8;
        *(uint4*)&qMh[r][c8] = *(const uint4*)(qMhb + (size_t)(q0 + r) * DD + c8);
        *(uint4*)&qMl[r][c8] = *(const uint4*)(qMlb + (size_t)(q0 + r) * DD + c8);
    }
    qq[t] = C1 * g_qMq[bh * SD + q0 + t];

    // per-warp rows: r0 = wid*32 + mt*16 + g (+8)
    float mr[4] = {-1e30f, -1e30f, -1e30f, -1e30f};
    float lr[4] = {0.f, 0.f, 0.f, 0.f};

    for (int n0 = 0; n0 < SD; n0 += 64) {
        __syncthreads();
        if (t < 128) {
            int r = t >> 1, c8 = (t & 1) * 8;
            // stage 64 K rows x 16 halfs per uint4... 64 rows x 8 uint4 = 512 loads
        }
        for (int idx = t; idx < 64 * 8; idx += 256) {
            int r = idx >> 3, c8 = (idx & 7) * 8;
            *(uint4*)&Kh[r][c8] = *(const uint4*)(Khb + (size_t)(n0 + r) * DD + c8);
            *(uint4*)&Kl[r][c8] = *(const uint4*)(Klb + (size_t)(n0 + r) * DD + c8);
        }
        if (t < 64) kks[t] = C1 * g_kMk[bh * SD + n0 + t];
        __syncthreads();

        float acc[2][8][4];
#pragma unroll
        for (int mt = 0; mt < 2; mt++)
#pragma unroll
            for (int nt = 0; nt < 8; nt++)
#pragma unroll
                for (int j = 0; j < 4; j++) acc[mt][nt][j] = 0.f;

#pragma unroll
        for (int kb = 0; kb < 64; kb += 16) {
            uint32_t ah[2][4], al[2][4];
            ldsm4(ah[0][0], ah[0][1], ah[0][2], ah[0][3], aH0 + kb * 2);
            ldsm4(ah[1][0], ah[1][1], ah[1][2], ah[1][3], aH1 + kb * 2);
            ldsm4(al[0][0], al[0][1], al[0][2], al[0][3], aL0 + kb * 2);
            ldsm4(al[1][0], al[1][1], al[1][2], al[1][3], aL1 + kb * 2);
#pragma unroll
            for (int p = 0; p < 4; p++) {
                uint32_t h0, h1, h2, h3, l0, l1, l2, l3;
                ldsm4(h0, h1, h2, h3, bHb + p * PSTRIDE + kb * 2);
                ldsm4(l0, l1, l2, l3, bLb + p * PSTRIDE + kb * 2);
#pragma unroll
                for (int mt = 0; mt < 2; mt++) {
                    mma16816(acc[mt][2 * p],     ah[mt][0], ah[mt][1], ah[mt][2], ah[mt][3], h0, h1);
                    mma16816(acc[mt][2 * p],     ah[mt][0], ah[mt][1], ah[mt][2], ah[mt][3], l0, l1);
                    mma16816(acc[mt][2 * p],     al[mt][0], al[mt][1], al[mt][2], al[mt][3], h0, h1);
                    mma16816(acc[mt][2 * p + 1], ah[mt][0], ah[mt][1], ah[mt][2], ah[mt][3], h2, h3);
                    mma16816(acc[mt][2 * p + 1], ah[mt][0], ah[mt][1], ah[mt][2], ah[mt][3], l2, l3);
                    mma16816(acc[mt][2 * p + 1], al[mt][0], al[mt][1], al[mt][2], al[mt][3], h2, h3);
                }
            }
        }

#pragma unroll
        for (int mt = 0; mt < 2; mt++) {
            const int rA = wid * 32 + mt * 16 + g, rB = rA + 8;
            const float qA = qq[rA], qB = qq[rB];
            float mA = -1e30f, mB = -1e30f;
#pragma unroll
            for (int nt = 0; nt < 8; nt++) {
                const float k0v = kks[nt * 8 + 2 * tg], k1v = kks[nt * 8 + 2 * tg + 1];
                float s0 = fmaf(C2, acc[mt][nt][0], -qA) - k0v;
                float s1 = fmaf(C2, acc[mt][nt][1], -qA) - k1v;
                float s2 = fmaf(C2, acc[mt][nt][2], -qB) - k0v;
                float s3 = fmaf(C2, acc[mt][nt][3], -qB) - k1v;
                acc[mt][nt][0] = s0; acc[mt][nt][1] = s1;
                acc[mt][nt][2] = s2; acc[mt][nt][3] = s3;
                mA = fmaxf(mA, fmaxf(s0, s1));
                mB = fmaxf(mB, fmaxf(s2, s3));
            }
            mA = fmaxf(mA, __shfl_xor_sync(0xffffffffu, mA, 1));
            mA = fmaxf(mA, __shfl_xor_sync(0xffffffffu, mA, 2));
            mB = fmaxf(mB, __shfl_xor_sync(0xffffffffu, mB, 1));
            mB = fmaxf(mB, __shfl_xor_sync(0xffffffffu, mB, 2));

            float SA = 0.f, SB = 0.f;
#pragma unroll
            for (int nt = 0; nt < 8; nt++) {
                float p0 = ex2(acc[mt][nt][0] - mA);
                float p1 = ex2(acc[mt][nt][1] - mA);
                float p2 = ex2(acc[mt][nt][2] - mB);
                float p3 = ex2(acc[mt][nt][3] - mB);
                __half2 hA = __floats2half2_rn(p0, p1);
                __half2 hB = __floats2half2_rn(p2, p3);
                __stcs((unsigned int*)(Pb + (size_t)(q0 + rA) * SD + n0 + nt * 8 + 2 * tg),
                       *(unsigned int*)&hA);
                __stcs((unsigned int*)(Pb + (size_t)(q0 + rB) * SD + n0 + nt * 8 + 2 * tg),
                       *(unsigned int*)&hB);
                SA += p0 + p1;
                SB += p2 + p3;
            }
            SA += __shfl_xor_sync(0xffffffffu, SA, 1);
            SA += __shfl_xor_sync(0xffffffffu, SA, 2);
            SB += __shfl_xor_sync(0xffffffffu, SB, 1);
            SB += __shfl_xor_sync(0xffffffffu, SB, 2);

            if (tg == 0) {
                g_blkm[((size_t)bh * SD + q0 + rA) * 32 + (n0 >> 6)] = mA;
                g_blkm[((size_t)bh * SD + q0 + rB) * 32 + (n0 >> 6)] = mB;
            }
            const int iA = 2 * mt, iB = 2 * mt + 1;
            float mnA = fmaxf(mr[iA], mA);
            lr[iA] = lr[iA] * ex2(mr[iA] - mnA) + SA * ex2(mA - mnA);
            mr[iA] = mnA;
            float mnB = fmaxf(mr[iB], mB);
            lr[iB] = lr[iB] * ex2(mr[iB] - mnB) + SB * ex2(mB - mnB);
            mr[iB] = mnB;
        }
    }
    if (tg == 0) {
#pragma unroll
        for (int mt = 0; mt < 2; mt++) {
            const int rA = wid * 32 + mt * 16 + g;
            g_rowm[bh * SD + q0 + rA]     = mr[2 * mt];
            g_rowl[bh * SD + q0 + rA]     = lr[2 * mt];
            g_rowm[bh * SD + q0 + rA + 8] = mr[2 * mt + 1];
            g_rowl[bh * SD + q0 + rA + 8] = lr[2 * mt + 1];
        }
    }
}

// ---------------- pass 2: attn = p'*c, ctx = attn @ V (64-col blocks) -----------
__global__ __launch_bounds__(256) void attn_ctx_mma(float* __restrict__ attn)
{
    __shared__ __half Ph[128][72];
    __shared__ __half Vs[64][72];
    __shared__ float c_s[128][32];
    const int bh = blockIdx.y, q0 = blockIdx.x * 128;
    const int b = bh >> 4, h = bh & 15;
    const __half* Pb = g_P + (size_t)bh * SD * SD;
    float* sc = attn + (size_t)bh * SD * SD;
    const __half* Vhb = g_Vh + (size_t)bh * SD * DD;
    const int t = threadIdx.x, wid = t >> 5, lane = t & 31;
    const int g = lane >> 2, tg = lane & 3;
    const int rA = wid * 16 + g, rB = rA + 8;

    const int aRow = wid * 16 + (lane & 15), aCol = (lane >> 4) * 8;
    const int bRow = ((lane >> 4) * 8) + (lane & 7);
    const int bCol = ((lane >> 3) & 1) * 8;
    const uint32_t aP = (uint32_t)__cvta_generic_to_shared(&Ph[aRow][aCol]);
    const uint32_t bV = (uint32_t)__cvta_generic_to_shared(&Vs[bRow][bCol]);
    const uint32_t PSTRIDE = 16 * 72 * 2;

    for (int idx = t; idx < 128 * 32; idx += 256) {
        int r = idx >> 5, blk = idx & 31;
        float mf = g_rowm[bh * SD + q0 + r];
        float lf = g_rowl[bh * SD + q0 + r];
        float mb = g_blkm[((size_t)bh * SD + q0 + r) * 32 + blk];
        c_s[r][blk] = ex2(mb - mf) / lf;
    }
    __syncthreads();

    float acc[8][4], accB[8][4];
#pragma unroll
    for (int nt = 0; nt < 8; nt++)
#pragma unroll
        for (int j = 0; j < 4; j++) { acc[nt][j] = 0.f; accB[nt][j] = 0.f; }

    for (int k0 = 0; k0 < SD; k0 += 64) {
        const int blk = k0 >> 6;
        for (int idx = t; idx < 1024; idx += 256) {
            int r = idx >> 3, c8 = (idx & 7) * 8;
            size_t gofs = (size_t)(q0 + r) * SD + k0 + c8;
            uint4 pv = __ldcs((const uint4*)(Pb + gofs));
            *(uint4*)&Ph[r][c8] = pv;
            const float cv = c_s[r][blk];
            const __half2* hp = (const __half2*)&pv;
            float2 f0 = __half22float2(hp[0]);
            float2 f1 = __half22float2(hp[1]);
            float2 f2 = __half22float2(hp[2]);
            float2 f3 = __half22float2(hp[3]);
            __stcs((float4*)(sc + gofs),
                   make_float4(f0.x * cv, f0.y * cv, f1.x * cv, f1.y * cv));
            __stcs((float4*)(sc + gofs + 4),
                   make_float4(f2.x * cv, f2.y * cv, f3.x * cv, f3.y * cv));
        }
        for (int idx = t; idx < 512; idx += 256) {
            int r = idx >> 3, c8 = (idx & 7) * 8;
            uint4 rh = *(const uint4*)(Vhb + (size_t)(k0 + r) * DD + c8);
            const __half* hp = (const __half*)&rh;
#pragma unroll
            for (int j = 0; j < 8; j++) Vs[c8 + j][r] = hp[j];
        }
        __syncthreads();
#pragma unroll
        for (int kb = 0; kb < 64; kb += 16) {
            uint32_t a0, a1, a2, a3;
            ldsm4(a0, a1, a2, a3, aP + kb * 2);
#pragma unroll
            for (int p = 0; p < 4; p++) {
                uint32_t h0, h1, h2, h3;
                ldsm4(h0, h1, h2, h3, bV + p * PSTRIDE + kb * 2);
                mma16816(accB[2 * p],     a0, a1, a2, a3, h0, h1);
                mma16816(accB[2 * p + 1], a0, a1, a2, a3, h2, h3);
            }
        }
        __syncthreads();
        {   // rescale partials for this 64-col softmax block
            const float ca = c_s[rA][blk], cb = c_s[rB][blk];
#pragma unroll
            for (int nt = 0; nt < 8; nt++) {
                acc[nt][0] = fmaf(accB[nt][0], ca, acc[nt][0]);
                acc[nt][1] = fmaf(accB[nt][1], ca, acc[nt][1]);
                acc[nt][2] = fmaf(accB[nt][2], cb, acc[nt][2]);
                acc[nt][3] = fmaf(accB[nt][3], cb, acc[nt][3]);
                accB[nt][0] = accB[nt][1] = accB[nt][2] = accB[nt][3] = 0.f;
            }
        }
    }
#pragma unroll
    for (int nt = 0; nt < 8; nt++) {
        const int c = h * DD + nt * 8 + 2 * tg;
        size_t iA = ((size_t)b * SD + q0 + rA) * ED + c;
        size_t iB = ((size_t)b * SD + q0 + rB) * ED + c;
        split_st(&g_ctxh[iA], &g_ctxl[iA], acc[nt][0], acc[nt][1]);
        split_st(&g_ctxh[iB], &g_ctxl[iB], acc[nt][2], acc[nt][3]);
    }
}

// ---------------- LayerNorm ------------------------------------------------------
__global__ __launch_bounds__(256) void ln_kernel(
    const float* __restrict__ gamma, const float* __restrict__ beta,
    float* __restrict__ out)
{
    const int row = blockIdx.x;
    const int t = threadIdx.x;
    float4 v = *(const float4*)(g_tmp + (size_t)row * ED + t * 4);
    float s  = v.x + v.y + v.z + v.w;
    float s2 = v.x * v.x + v.y * v.y + v.z * v.z + v.w * v.w;
#pragma unroll
    for (int o = 16; o > 0; o >>= 1) {
        s  += __shfl_xor_sync(0xffffffffu, s, o);
        s2 += __shfl_xor_sync(0xffffffffu, s2, o);
    }
    __shared__ float ws[8], ws2[8];
    if ((t & 31) == 0) { ws[t >> 5] = s; ws2[t >> 5] = s2; }
    __syncthreads();
    if (t < 32) {
        float a = (t < 8) ? ws[t] : 0.f;
        float b = (t < 8) ? ws2[t] : 0.f;
#pragma unroll
        for (int o = 4; o > 0; o >>= 1) {
            a += __shfl_xor_sync(0xffffffffu, a, o);
            b += __shfl_xor_sync(0xffffffffu, b, o);
        }
        if (t == 0) { ws[0] = a; ws2[0] = b; }
    }
    __syncthreads();
    const float mu  = ws[0] * (1.f / ED);
    const float var = ws2[0] * (1.f / ED) - mu * mu;
    const float inv = rsqrtf(var + 1e-5f);
    const int c = t * 4;
    float4 ga = *(const float4*)(gamma + c);
    float4 be = *(const float4*)(beta + c);
    float4 o4;
    o4.x = (v.x - mu) * inv * ga.x + be.x;
    o4.y = (v.y - mu) * inv * ga.y + be.y;
    o4.z = (v.z - mu) * inv * ga.z + be.z;
    o4.w = (v.w - mu) * inv * ga.w + be.w;
    *(float4*)(out + (size_t)row * ED + c) = o4;
}

// ---------------- launch ---------------------------------------------------------
extern "C" void kernel_launch(void* const* d_in, const int* in_sizes, int n_in,
                              void* d_out, int out_size)
{
    const float* x     = (const float*)d_in[0];
    const float* Wq    = (const float*)d_in[1];
    const float* bq    = (const float*)d_in[2];
    const float* Wk    = (const float*)d_in[3];
    const float* bk    = (const float*)d_in[4];
    const float* Wv    = (const float*)d_in[5];
    const float* bv    = (const float*)d_in[6];
    const float* M     = (const float*)d_in[7];
    const float* Wo    = (const float*)d_in[8];
    const float* bo    = (const float*)d_in[9];
    const float* gamma = (const float*)d_in[10];
    const float* beta  = (const float*)d_in[11];

    float* outp  = (float*)d_out;
    float* attnp = outp + (size_t)ROWS * ED;   // tuple order: out, then attn

    cudaFuncSetAttribute(scores_mma,
                         cudaFuncAttributeMaxDynamicSharedMemorySize, (int)SC_SMEM);
    cudaFuncSetAttribute(qm_mma,
                         cudaFuncAttributeMaxDynamicSharedMemorySize, (int)QM_SMEM);

    dim3 gProj(ED / 128, ROWS / 128);            // (8, 32)
    dim3 gProjQK(ED / 128, ROWS / 128, 2);       // (8, 32, 2)

    prep_kernel<<<(N4X + 4 * N4W) / 256, 256>>>(x, Wq, Wk, Wv, Wo);   // idx 0
    hgemm_qk<<<gProjQK, 256>>>(bq, bk);                               // idx 1
    qm_mma<<<dim3(BHS / 128, 2), 256, QM_SMEM>>>(M);                  // idx 2
    scores_mma<<<dim3(SD / 256, BH), 256, SC_SMEM>>>();               // idx 3  <- profiled
    hgemm_v<<<gProj, 256>>>(bv);                                      // idx 4
    attn_ctx_mma<<<dim3(SD / 128, BH), 256>>>(attnp);                 // idx 5
    hgemm_o<<<gProj, 256>>>(bo, x);                                   // idx 6
    ln_kernel<<<ROWS, 256>>>(gamma, beta, outp);                      // idx 7
}

// round 13
// speedup vs baseline: 1.1289x; 1.1289x over previous
#include <cuda_runtime.h>
#include <cuda_fp16.h>
#include <math.h>
#include <stdint.h>

#define SD 2048
#define ED 1024
#define HD 16
#define DD 64
#define BD 2
#define BH (BD*HD)     /* 32 */
#define ROWS (BD*SD)   /* 4096 */
#define BHS (BH*SD)    /* 65536 */

#define C1 11.5415603f   /* 8*log2(e) */
#define C2 23.0831206f   /* 16*log2(e) */

#define N4X (ROWS * ED / 4)   /* 1048576 */
#define N4W (ED * ED / 4)     /*  262144 */

// ---------------- scratch ----------------
__device__ __half g_xh[(size_t)ROWS * ED];
__device__ __half g_xl[(size_t)ROWS * ED];
__device__ __half g_wqh[(size_t)ED * ED];
__device__ __half g_wql[(size_t)ED * ED];
__device__ __half g_wkh[(size_t)ED * ED];
__device__ __half g_wkl[(size_t)ED * ED];
__device__ __half g_wvh[(size_t)ED * ED];
__device__ __half g_woh[(size_t)ED * ED];
__device__ __half g_Qh[(size_t)BHS * DD];
__device__ __half g_Ql[(size_t)BHS * DD];
__device__ __half g_Kh[(size_t)BHS * DD];
__device__ __half g_Kl[(size_t)BHS * DD];
__device__ __half g_Vh[(size_t)BHS * DD];
__device__ __half g_qMh[(size_t)BHS * DD];
__device__ __half g_qMl[(size_t)BHS * DD];
__device__ float  g_qMq[BHS];
__device__ float  g_kMk[BHS];
__device__ float  g_rowm[BHS];
__device__ float  g_rowl[BHS];
__device__ float  g_blkm[(size_t)32 * BHS];      /* [blk][bh*SD+row] transposed */
__device__ __half g_P[(size_t)BH * SD * SD];     /* 268 MB: unnormalized probs fp16 */
__device__ __half g_ctxh[(size_t)ROWS * ED];
__device__ __half g_ctxl[(size_t)ROWS * ED];
__device__ float  g_tmp[(size_t)ROWS * ED];

// ---------------- helpers ----------------
__device__ __forceinline__ float ex2(float x) {
    float y; asm("ex2.approx.f32 %0, %1;" : "=f"(y) : "f"(x)); return y;
}

__device__ __forceinline__ void mma16816(float (&c)[4],
    uint32_t a0, uint32_t a1, uint32_t a2, uint32_t a3, uint32_t b0, uint32_t b1)
{
    asm volatile(
        "mma.sync.aligned.m16n8k16.row.col.f32.f16.f16.f32 "
        "{%0,%1,%2,%3}, {%4,%5,%6,%7}, {%8,%9}, {%0,%1,%2,%3};"
        : "+f"(c[0]), "+f"(c[1]), "+f"(c[2]), "+f"(c[3])
        : "r"(a0), "r"(a1), "r"(a2), "r"(a3), "r"(b0), "r"(b1));
}

__device__ __forceinline__ void ldsm4(uint32_t& r0, uint32_t& r1, uint32_t& r2, uint32_t& r3,
                                      uint32_t addr)
{
    asm volatile("ldmatrix.sync.aligned.m8n8.x4.shared.b16 {%0,%1,%2,%3}, [%4];"
        : "=r"(r0), "=r"(r1), "=r"(r2), "=r"(r3) : "r"(addr));
}

__device__ __forceinline__ uint32_t ld_u32(const __half* p) {
    return *reinterpret_cast<const uint32_t*>(p);
}

__device__ __forceinline__ void split_st(__half* ph, __half* pl, float x, float y) {
    __half hx = __float2half_rn(x), hy = __float2half_rn(y);
    *reinterpret_cast<__half2*>(ph) = __halves2half2(hx, hy);
    __half lx = __float2half_rn(x - __half2float(hx));
    __half ly = __float2half_rn(y - __half2float(hy));
    *reinterpret_cast<__half2*>(pl) = __halves2half2(lx, ly);
}

// ---------------- fused converter ----------------
__global__ __launch_bounds__(256) void prep_kernel(
    const float* __restrict__ x,
    const float* __restrict__ Wq, const float* __restrict__ Wk,
    const float* __restrict__ Wv, const float* __restrict__ Wo)
{
    int i = blockIdx.x * 256 + threadIdx.x;
    if (i < N4X) {
        float4 v = ((const float4*)x)[i];
        split_st(g_xh + 4 * (size_t)i,     g_xl + 4 * (size_t)i,     v.x, v.y);
        split_st(g_xh + 4 * (size_t)i + 2, g_xl + 4 * (size_t)i + 2, v.z, v.w);
        return;
    }
    int j = i - N4X;
    int w = j / N4W, o = j % N4W;
    if (w == 0) {
        float4 v = ((const float4*)Wq)[o];
        split_st(g_wqh + 4 * (size_t)o,     g_wql + 4 * (size_t)o,     v.x, v.y);
        split_st(g_wqh + 4 * (size_t)o + 2, g_wql + 4 * (size_t)o + 2, v.z, v.w);
    } else if (w == 1) {
        float4 v = ((const float4*)Wk)[o];
        split_st(g_wkh + 4 * (size_t)o,     g_wkl + 4 * (size_t)o,     v.x, v.y);
        split_st(g_wkh + 4 * (size_t)o + 2, g_wkl + 4 * (size_t)o + 2, v.z, v.w);
    } else if (w == 2) {
        float4 v = ((const float4*)Wv)[o];
        __half2* d = (__half2*)(g_wvh + 4 * (size_t)o);
        d[0] = __floats2half2_rn(v.x, v.y);
        d[1] = __floats2half2_rn(v.z, v.w);
    } else {
        float4 v = ((const float4*)Wo)[o];
        __half2* d = (__half2*)(g_woh + 4 * (size_t)o);
        d[0] = __floats2half2_rn(v.x, v.y);
        d[1] = __floats2half2_rn(v.z, v.w);
    }
}

// ---------------- 128x128 HGEMM core (unchanged) ----------------
template <int MODE, int NSPLIT>
__device__ __forceinline__ void hgemm_core(
    char* smem,
    const __half* __restrict__ Ahg, const __half* __restrict__ Alg,
    const __half* __restrict__ Bhg, const __half* __restrict__ Blg,
    float* __restrict__ C, __half* __restrict__ Ch, __half* __restrict__ Cl,
    const float* __restrict__ bias, const float* __restrict__ resid)
{
    __half (*Ah)[40] = (__half(*)[40])smem;
    __half (*Bh)[40] = Ah + 128;
    __half (*Al)[40] = Ah + 256;
    __half (*Bl)[40] = Ah + 384;
    const int t = threadIdx.x;
    const int wid = t >> 5, lane = t & 31;
    const int g = lane >> 2, tg = lane & 3;
    const int wr = wid >> 1, wc = wid & 1;
    const int row0 = blockIdx.y * 128, col0 = blockIdx.x * 128;
    const int lr = t >> 1, lq = (t & 1) * 16;
    const __half* Aph = Ahg + (size_t)(row0 + lr) * ED + lq;
    const __half* Apl = (NSPLIT >= 2) ? Alg + (size_t)(row0 + lr) * ED + lq : nullptr;
    const __half* Bph = Bhg + (size_t)(col0 + lr) * ED + lq;
    const __half* Bpl = (NSPLIT >= 3) ? Blg + (size_t)(col0 + lr) * ED + lq : nullptr;

    float acc[2][8][4];
#pragma unroll
    for (int mt = 0; mt < 2; mt++)
#pragma unroll
        for (int nt = 0; nt < 8; nt++)
#pragma unroll
            for (int j = 0; j < 4; j++) acc[mt][nt][j] = 0.f;

    uint4 va0 = *(const uint4*)(Aph),  va1 = *(const uint4*)(Aph + 8);
    uint4 vb0 = *(const uint4*)(Bph),  vb1 = *(const uint4*)(Bph + 8);
    uint4 vl0, vl1, vm0, vm1;
    if (NSPLIT >= 2) { vl0 = *(const uint4*)(Apl); vl1 = *(const uint4*)(Apl + 8); }
    if (NSPLIT >= 3) { vm0 = *(const uint4*)(Bpl); vm1 = *(const uint4*)(Bpl + 8); }

    for (int k0 = 0; k0 < ED; k0 += 32) {
        *(uint4*)&Ah[lr][lq] = va0; *(uint4*)&Ah[lr][lq + 8] = va1;
        *(uint4*)&Bh[lr][lq] = vb0; *(uint4*)&Bh[lr][lq + 8] = vb1;
        if (NSPLIT >= 2) { *(uint4*)&Al[lr][lq] = vl0; *(uint4*)&Al[lr][lq + 8] = vl1; }
        if (NSPLIT >= 3) { *(uint4*)&Bl[lr][lq] = vm0; *(uint4*)&Bl[lr][lq + 8] = vm1; }
        __syncthreads();
        if (k0 + 32 < ED) {
            va0 = *(const uint4*)(Aph + k0 + 32); va1 = *(const uint4*)(Aph + k0 + 40);
            vb0 = *(const uint4*)(Bph + k0 + 32); vb1 = *(const uint4*)(Bph + k0 + 40);
            if (NSPLIT >= 2) { vl0 = *(const uint4*)(Apl + k0 + 32); vl1 = *(const uint4*)(Apl + k0 + 40); }
            if (NSPLIT >= 3) { vm0 = *(const uint4*)(Bpl + k0 + 32); vm1 = *(const uint4*)(Bpl + k0 + 40); }
        }
#pragma unroll
        for (int ks = 0; ks < 2; ks++) {
            const int kb = ks * 16;
            uint32_t ahi[2][4], alo[2][4];
#pragma unroll
            for (int mt = 0; mt < 2; mt++) {
                const int r0 = wr * 32 + mt * 16;
                ahi[mt][0] = ld_u32(&Ah[r0 + g][kb + 2 * tg]);
                ahi[mt][1] = ld_u32(&Ah[r0 + g + 8][kb + 2 * tg]);
                ahi[mt][2] = ld_u32(&Ah[r0 + g][kb + 2 * tg + 8]);
                ahi[mt][3] = ld_u32(&Ah[r0 + g + 8][kb + 2 * tg + 8]);
                if (NSPLIT >= 2) {
                    alo[mt][0] = ld_u32(&Al[r0 + g][kb + 2 * tg]);
                    alo[mt][1] = ld_u32(&Al[r0 + g + 8][kb + 2 * tg]);
                    alo[mt][2] = ld_u32(&Al[r0 + g][kb + 2 * tg + 8]);
                    alo[mt][3] = ld_u32(&Al[r0 + g + 8][kb + 2 * tg + 8]);
                }
            }
#pragma unroll
            for (int nt = 0; nt < 8; nt++) {
                const int nr = wc * 64 + nt * 8 + g;
                uint32_t bh0 = ld_u32(&Bh[nr][kb + 2 * tg]);
                uint32_t bh1 = ld_u32(&Bh[nr][kb + 2 * tg + 8]);
#pragma unroll
                for (int mt = 0; mt < 2; mt++) {
                    mma16816(acc[mt][nt], ahi[mt][0], ahi[mt][1], ahi[mt][2], ahi[mt][3], bh0, bh1);
                    if (NSPLIT >= 3) {
                        uint32_t bl0 = ld_u32(&Bl[nr][kb + 2 * tg]);
                        uint32_t bl1 = ld_u32(&Bl[nr][kb + 2 * tg + 8]);
                        mma16816(acc[mt][nt], ahi[mt][0], ahi[mt][1], ahi[mt][2], ahi[mt][3], bl0, bl1);
                    }
                    if (NSPLIT >= 2)
                        mma16816(acc[mt][nt], alo[mt][0], alo[mt][1], alo[mt][2], alo[mt][3], bh0, bh1);
                }
            }
        }
        __syncthreads();
    }

#pragma unroll
    for (int mt = 0; mt < 2; mt++) {
        const int rA = row0 + wr * 32 + mt * 16 + g;
        const int rB = rA + 8;
#pragma unroll
        for (int nt = 0; nt < 8; nt++) {
            const int c = col0 + wc * 64 + nt * 8 + 2 * tg;
            const float b0 = bias[c], b1 = bias[c + 1];
            float v00 = acc[mt][nt][0] + b0, v01 = acc[mt][nt][1] + b1;
            float v10 = acc[mt][nt][2] + b0, v11 = acc[mt][nt][3] + b1;
            if (MODE == 3) {
                size_t iA = (size_t)rA * ED + c;
                size_t iB = (size_t)rB * ED + c;
                float2 r0 = *(const float2*)&resid[iA];
                float2 r1 = *(const float2*)&resid[iB];
                *(float2*)&C[iA] = make_float2(v00 + r0.x, v01 + r0.y);
                *(float2*)&C[iB] = make_float2(v10 + r1.x, v11 + r1.y);
            } else {
                const int h_ = c >> 6, d_ = c & 63;
                size_t iA = (((size_t)(rA >> 11) * HD + h_) * SD + (rA & (SD - 1))) * DD + d_;
                size_t iB = (((size_t)(rB >> 11) * HD + h_) * SD + (rB & (SD - 1))) * DD + d_;
                if (MODE == 4) {
                    split_st(&Ch[iA], &Cl[iA], v00, v01);
                    split_st(&Ch[iB], &Cl[iB], v10, v11);
                }
                if (MODE == 2) {
                    *(__half2*)&Ch[iA] = __floats2half2_rn(v00, v01);
                    *(__half2*)&Ch[iB] = __floats2half2_rn(v10, v11);
                }
            }
        }
    }
}

__global__ __launch_bounds__(256) void hgemm_qk(
    const float* __restrict__ bq, const float* __restrict__ bk)
{
    __shared__ char smem[4 * 128 * 40 * 2];
    if (blockIdx.z == 0)
        hgemm_core<4, 3>(smem, g_xh, g_xl, g_wqh, g_wql, nullptr, g_Qh, g_Ql, bq, nullptr);
    else
        hgemm_core<4, 3>(smem, g_xh, g_xl, g_wkh, g_wkl, nullptr, g_Kh, g_Kl, bk, nullptr);
}

__global__ __launch_bounds__(256) void hgemm_v(const float* __restrict__ bv)
{
    __shared__ char smem[2 * 128 * 40 * 2];
    hgemm_core<2, 1>(smem, g_xh, nullptr, g_wvh, nullptr, nullptr, g_Vh, nullptr, bv, nullptr);
}

__global__ __launch_bounds__(256) void hgemm_o(
    const float* __restrict__ bo, const float* __restrict__ resid)
{
    __shared__ char smem[3 * 128 * 40 * 2];
    hgemm_core<3, 2>(smem, g_ctxh, g_ctxl, g_woh, nullptr, g_tmp, nullptr, nullptr, bo, resid);
}

// ---------------- qm via mma (unchanged) ----------------
#define QM_SMEM (size_t)((128 + 128 + 64 + 64) * 72 * 2)
__global__ __launch_bounds__(256) void qm_mma(const float* __restrict__ M)
{
    extern __shared__ __half qsm[];
    __half (*Qh_s)[72] = (__half(*)[72])qsm;
    __half (*Ql_s)[72] = Qh_s + 128;
    __half (*Mh_s)[72] = Qh_s + 256;
    __half (*Ml_s)[72] = Qh_s + 320;
    const int t = threadIdx.x, wid = t >> 5, lane = t & 31;
    const int g = lane >> 2, tg = lane & 3;
    const int r0 = blockIdx.x * 128;
    const bool isQ = (blockIdx.y == 0);
    const __half* Ahg = isQ ? g_Qh : g_Kh;
    const __half* Alg = isQ ? g_Ql : g_Kl;

    for (int idx = t; idx < 64 * 64; idx += 256) {
        int d = idx >> 6, e = idx & 63;
        float v = M[d * 64 + e];
        __half hv = __float2half_rn(v);
        Mh_s[e][d] = hv;
        Ml_s[e][d] = __float2half_rn(v - __half2float(hv));
    }
    for (int idx = t; idx < 128 * 8; idx += 256) {
        int r = idx >> 3, c8 = (idx & 7) * 8;
        *(uint4*)&Qh_s[r][c8] = *(const uint4*)(Ahg + (size_t)(r0 + r) * DD + c8);
        *(uint4*)&Ql_s[r][c8] = *(const uint4*)(Alg + (size_t)(r0 + r) * DD + c8);
    }
    __syncthreads();

    const int rA = wid * 16 + g, rB = rA + 8;
    float acc[8][4];
#pragma unroll
    for (int nt = 0; nt < 8; nt++)
#pragma unroll
        for (int j = 0; j < 4; j++) acc[nt][j] = 0.f;

#pragma unroll
    for (int kb = 0; kb < 64; kb += 16) {
        uint32_t ah0 = ld_u32(&Qh_s[rA][kb + 2 * tg]);
        uint32_t ah1 = ld_u32(&Qh_s[rB][kb + 2 * tg]);
        uint32_t ah2 = ld_u32(&Qh_s[rA][kb + 2 * tg + 8]);
        uint32_t ah3 = ld_u32(&Qh_s[rB][kb + 2 * tg + 8]);
        uint32_t al0 = ld_u32(&Ql_s[rA][kb + 2 * tg]);
        uint32_t al1 = ld_u32(&Ql_s[rB][kb + 2 * tg]);
        uint32_t al2 = ld_u32(&Ql_s[rA][kb + 2 * tg + 8]);
        uint32_t al3 = ld_u32(&Ql_s[rB][kb + 2 * tg + 8]);
#pragma unroll
        for (int nt = 0; nt < 8; nt++) {
            const int nr = nt * 8 + g;
            uint32_t bh0 = ld_u32(&Mh_s[nr][kb + 2 * tg]);
            uint32_t bh1 = ld_u32(&Mh_s[nr][kb + 2 * tg + 8]);
            uint32_t bl0 = ld_u32(&Ml_s[nr][kb + 2 * tg]);
            uint32_t bl1 = ld_u32(&Ml_s[nr][kb + 2 * tg + 8]);
            mma16816(acc[nt], ah0, ah1, ah2, ah3, bh0, bh1);
            mma16816(acc[nt], ah0, ah1, ah2, ah3, bl0, bl1);
            mma16816(acc[nt], al0, al1, al2, al3, bh0, bh1);
        }
    }

    float dotA = 0.f, dotB = 0.f;
#pragma unroll
    for (int nt = 0; nt < 8; nt++) {
        const int c0 = nt * 8 + 2 * tg;
        if (isQ) {
            split_st(&g_qMh[(size_t)(r0 + rA) * DD + c0], &g_qMl[(size_t)(r0 + rA) * DD + c0],
                     acc[nt][0], acc[nt][1]);
            split_st(&g_qMh[(size_t)(r0 + rB) * DD + c0], &g_qMl[(size_t)(r0 + rB) * DD + c0],
                     acc[nt][2], acc[nt][3]);
        }
        float qA0 = __half2float(Qh_s[rA][c0])     + __half2float(Ql_s[rA][c0]);
        float qA1 = __half2float(Qh_s[rA][c0 + 1]) + __half2float(Ql_s[rA][c0 + 1]);
        float qB0 = __half2float(Qh_s[rB][c0])     + __half2float(Ql_s[rB][c0]);
        float qB1 = __half2float(Qh_s[rB][c0 + 1]) + __half2float(Ql_s[rB][c0 + 1]);
        dotA = fmaf(acc[nt][0], qA0, fmaf(acc[nt][1], qA1, dotA));
        dotB = fmaf(acc[nt][2], qB0, fmaf(acc[nt][3], qB1, dotB));
    }
    dotA += __shfl_xor_sync(0xffffffffu, dotA, 1);
    dotA += __shfl_xor_sync(0xffffffffu, dotA, 2);
    dotB += __shfl_xor_sync(0xffffffffu, dotB, 1);
    dotB += __shfl_xor_sync(0xffffffffu, dotB, 2);
    if (tg == 0) {
        float* dst = isQ ? g_qMq : g_kMk;
        dst[r0 + rA] = dotA;
        dst[r0 + rB] = dotB;
    }
}

// ---------------- pass 1: 256 q-rows x 64 k-cols per iter (unchanged core) ------
#define SC_SMEM (size_t)((256 + 256 + 64 + 64) * 72 * 2)   /* 92160 B */
__global__ __launch_bounds__(256) void scores_mma()
{
    extern __shared__ __half smx[];
    __half (*qMh)[72] = (__half(*)[72])smx;       // [256][72]
    __half (*qMl)[72] = qMh + 256;                // [256][72]
    __half (*Kh)[72]  = qMh + 512;                // [64][72]
    __half (*Kl)[72]  = qMh + 576;                // [64][72]
    __shared__ float qq[256], kks[64];

    const int bh = blockIdx.y, q0 = blockIdx.x * 256;
    const __half* qMhb = g_qMh + (size_t)bh * SD * DD;
    const __half* qMlb = g_qMl + (size_t)bh * SD * DD;
    const __half* Khb  = g_Kh  + (size_t)bh * SD * DD;
    const __half* Klb  = g_Kl  + (size_t)bh * SD * DD;
    __half* Pb = g_P + (size_t)bh * SD * SD;
    const int t = threadIdx.x, wid = t >> 5, lane = t & 31;
    const int g = lane >> 2, tg = lane & 3;

    const int aR = wid * 32 + (lane & 15), aC = (lane >> 4) * 8;
    const int bRow = ((lane >> 4) * 8) + (lane & 7);
    const int bCol = ((lane >> 3) & 1) * 8;
    const uint32_t aH0 = (uint32_t)__cvta_generic_to_shared(&qMh[aR][aC]);
    const uint32_t aH1 = (uint32_t)__cvta_generic_to_shared(&qMh[aR + 16][aC]);
    const uint32_t aL0 = (uint32_t)__cvta_generic_to_shared(&qMl[aR][aC]);
    const uint32_t aL1 = (uint32_t)__cvta_generic_to_shared(&qMl[aR + 16][aC]);
    const uint32_t bHb = (uint32_t)__cvta_generic_to_shared(&Kh[bRow][bCol]);
    const uint32_t bLb = (uint32_t)__cvta_generic_to_shared(&Kl[bRow][bCol]);
    const uint32_t PSTRIDE = 16 * 72 * 2;

    for (int idx = t; idx < 256 * 8; idx += 256) {
        int r = idx >> 3, c8 = (idx & 7) * 8;
        *(uint4*)&qMh[r][c8] = *(const uint4*)(qMhb + (size_t)(q0 + r) * DD + c8);
        *(uint4*)&qMl[r][c8] = *(const uint4*)(qMlb + (size_t)(q0 + r) * DD + c8);
    }
    qq[t] = C1 * g_qMq[bh * SD + q0 + t];

    float mr[4] = {-1e30f, -1e30f, -1e30f, -1e30f};
    float lr[4] = {0.f, 0.f, 0.f, 0.f};

    for (int n0 = 0; n0 < SD; n0 += 64) {
        __syncthreads();
        for (int idx = t; idx < 64 * 8; idx += 256) {
            int r = idx >> 3, c8 = (idx & 7) * 8;
            *(uint4*)&Kh[r][c8] = *(const uint4*)(Khb + (size_t)(n0 + r) * DD + c8);
            *(uint4*)&Kl[r][c8] = *(const uint4*)(Klb + (size_t)(n0 + r) * DD + c8);
        }
        if (t < 64) kks[t] = C1 * g_kMk[bh * SD + n0 + t];
        __syncthreads();

        float acc[2][8][4];
#pragma unroll
        for (int mt = 0; mt < 2; mt++)
#pragma unroll
            for (int nt = 0; nt < 8; nt++)
#pragma unroll
                for (int j = 0; j < 4; j++) acc[mt][nt][j] = 0.f;

#pragma unroll
        for (int kb = 0; kb < 64; kb += 16) {
            uint32_t ah[2][4], al[2][4];
            ldsm4(ah[0][0], ah[0][1], ah[0][2], ah[0][3], aH0 + kb * 2);
            ldsm4(ah[1][0], ah[1][1], ah[1][2], ah[1][3], aH1 + kb * 2);
            ldsm4(al[0][0], al[0][1], al[0][2], al[0][3], aL0 + kb * 2);
            ldsm4(al[1][0], al[1][1], al[1][2], al[1][3], aL1 + kb * 2);
#pragma unroll
            for (int p = 0; p < 4; p++) {
                uint32_t h0, h1, h2, h3, l0, l1, l2, l3;
                ldsm4(h0, h1, h2, h3, bHb + p * PSTRIDE + kb * 2);
                ldsm4(l0, l1, l2, l3, bLb + p * PSTRIDE + kb * 2);
#pragma unroll
                for (int mt = 0; mt < 2; mt++) {
                    mma16816(acc[mt][2 * p],     ah[mt][0], ah[mt][1], ah[mt][2], ah[mt][3], h0, h1);
                    mma16816(acc[mt][2 * p],     ah[mt][0], ah[mt][1], ah[mt][2], ah[mt][3], l0, l1);
                    mma16816(acc[mt][2 * p],     al[mt][0], al[mt][1], al[mt][2], al[mt][3], h0, h1);
                    mma16816(acc[mt][2 * p + 1], ah[mt][0], ah[mt][1], ah[mt][2], ah[mt][3], h2, h3);
                    mma16816(acc[mt][2 * p + 1], ah[mt][0], ah[mt][1], ah[mt][2], ah[mt][3], l2, l3);
                    mma16816(acc[mt][2 * p + 1], al[mt][0], al[mt][1], al[mt][2], al[mt][3], h2, h3);
                }
            }
        }

#pragma unroll
        for (int mt = 0; mt < 2; mt++) {
            const int rA = wid * 32 + mt * 16 + g, rB = rA + 8;
            const float qA = qq[rA], qB = qq[rB];
            float mA = -1e30f, mB = -1e30f;
#pragma unroll
            for (int nt = 0; nt < 8; nt++) {
                const float k0v = kks[nt * 8 + 2 * tg], k1v = kks[nt * 8 + 2 * tg + 1];
                float s0 = fmaf(C2, acc[mt][nt][0], -qA) - k0v;
                float s1 = fmaf(C2, acc[mt][nt][1], -qA) - k1v;
                float s2 = fmaf(C2, acc[mt][nt][2], -qB) - k0v;
                float s3 = fmaf(C2, acc[mt][nt][3], -qB) - k1v;
                acc[mt][nt][0] = s0; acc[mt][nt][1] = s1;
                acc[mt][nt][2] = s2; acc[mt][nt][3] = s3;
                mA = fmaxf(mA, fmaxf(s0, s1));
                mB = fmaxf(mB, fmaxf(s2, s3));
            }
            mA = fmaxf(mA, __shfl_xor_sync(0xffffffffu, mA, 1));
            mA = fmaxf(mA, __shfl_xor_sync(0xffffffffu, mA, 2));
            mB = fmaxf(mB, __shfl_xor_sync(0xffffffffu, mB, 1));
            mB = fmaxf(mB, __shfl_xor_sync(0xffffffffu, mB, 2));

            float SA = 0.f, SB = 0.f;
#pragma unroll
            for (int nt = 0; nt < 8; nt++) {
                float p0 = ex2(acc[mt][nt][0] - mA);
                float p1 = ex2(acc[mt][nt][1] - mA);
                float p2 = ex2(acc[mt][nt][2] - mB);
                float p3 = ex2(acc[mt][nt][3] - mB);
                __half2 hA = __floats2half2_rn(p0, p1);
                __half2 hB = __floats2half2_rn(p2, p3);
                __stcs((unsigned int*)(Pb + (size_t)(q0 + rA) * SD + n0 + nt * 8 + 2 * tg),
                       *(unsigned int*)&hA);
                __stcs((unsigned int*)(Pb + (size_t)(q0 + rB) * SD + n0 + nt * 8 + 2 * tg),
                       *(unsigned int*)&hB);
                SA += p0 + p1;
                SB += p2 + p3;
            }
            SA += __shfl_xor_sync(0xffffffffu, SA, 1);
            SA += __shfl_xor_sync(0xffffffffu, SA, 2);
            SB += __shfl_xor_sync(0xffffffffu, SB, 1);
            SB += __shfl_xor_sync(0xffffffffu, SB, 2);

            if (tg == 0) {
                g_blkm[(size_t)(n0 >> 6) * BHS + bh * SD + q0 + rA] = mA;
                g_blkm[(size_t)(n0 >> 6) * BHS + bh * SD + q0 + rB] = mB;
            }
            const int iA = 2 * mt, iB = 2 * mt + 1;
            float mnA = fmaxf(mr[iA], mA);
            lr[iA] = lr[iA] * ex2(mr[iA] - mnA) + SA * ex2(mA - mnA);
            mr[iA] = mnA;
            float mnB = fmaxf(mr[iB], mB);
            lr[iB] = lr[iB] * ex2(mr[iB] - mnB) + SB * ex2(mB - mnB);
            mr[iB] = mnB;
        }
    }
    if (tg == 0) {
#pragma unroll
        for (int mt = 0; mt < 2; mt++) {
            const int rA = wid * 32 + mt * 16 + g;
            g_rowm[bh * SD + q0 + rA]     = mr[2 * mt];
            g_rowl[bh * SD + q0 + rA]     = lr[2 * mt];
            g_rowm[bh * SD + q0 + rA + 8] = mr[2 * mt + 1];
            g_rowl[bh * SD + q0 + rA + 8] = lr[2 * mt + 1];
        }
    }
}

// ---------------- pass 2: 256 rows/block; P scaled at staging (no accB) ---------
#define AC_SMEM (size_t)((256 + 64) * 72 * 2)   /* 46080 B */
__global__ __launch_bounds__(256) void attn_ctx_mma(float* __restrict__ attn)
{
    extern __shared__ __half acsm[];
    __half (*Ph)[72] = (__half(*)[72])acsm;   // [256][72] holds p*c (scaled)
    __half (*Vs)[72] = Ph + 256;              // [64][72]
    __shared__ float c_blk[256], rm_s[256], rli_s[256];
    const int bh = blockIdx.y, q0 = blockIdx.x * 256;
    const int b = bh >> 4, h = bh & 15;
    const __half* Pb = g_P + (size_t)bh * SD * SD;
    float* sc = attn + (size_t)bh * SD * SD;
    const __half* Vhb = g_Vh + (size_t)bh * SD * DD;
    const int t = threadIdx.x, wid = t >> 5, lane = t & 31;
    const int g = lane >> 2, tg = lane & 3;

    const int aRow = wid * 32 + (lane & 15), aCol = (lane >> 4) * 8;
    const int bRow = ((lane >> 4) * 8) + (lane & 7);
    const int bCol = ((lane >> 3) & 1) * 8;
    const uint32_t aP0 = (uint32_t)__cvta_generic_to_shared(&Ph[aRow][aCol]);
    const uint32_t aP1 = (uint32_t)__cvta_generic_to_shared(&Ph[aRow + 16][aCol]);
    const uint32_t bV  = (uint32_t)__cvta_generic_to_shared(&Vs[bRow][bCol]);
    const uint32_t PSTRIDE = 16 * 72 * 2;

    rm_s[t]  = g_rowm[bh * SD + q0 + t];
    rli_s[t] = 1.f / g_rowl[bh * SD + q0 + t];

    float acc[2][8][4];
#pragma unroll
    for (int mt = 0; mt < 2; mt++)
#pragma unroll
        for (int nt = 0; nt < 8; nt++)
#pragma unroll
            for (int j = 0; j < 4; j++) acc[mt][nt][j] = 0.f;

    for (int k0 = 0; k0 < SD; k0 += 64) {
        const int blk = k0 >> 6;
        __syncthreads();   // prev MMA done; smem + c_blk reusable (also covers rm_s init)
        c_blk[t] = ex2(g_blkm[(size_t)blk * BHS + bh * SD + q0 + t] - rm_s[t]) * rli_s[t];
        for (int idx = t; idx < 512; idx += 256) {
            int r = idx >> 3, c8 = (idx & 7) * 8;
            uint4 rh = *(const uint4*)(Vhb + (size_t)(k0 + r) * DD + c8);
            const __half* hp = (const __half*)&rh;
#pragma unroll
            for (int j = 0; j < 8; j++) Vs[c8 + j][r] = hp[j];
        }
        __syncthreads();   // c_blk + Vs visible
        for (int idx = t; idx < 2048; idx += 256) {
            int r = idx >> 3, c8 = (idx & 7) * 8;
            size_t gofs = (size_t)(q0 + r) * SD + k0 + c8;
            uint4 pv = __ldcs((const uint4*)(Pb + gofs));
            const float cv = c_blk[r];
            const __half2* hp = (const __half2*)&pv;
            float2 f0 = __half22float2(hp[0]);
            float2 f1 = __half22float2(hp[1]);
            float2 f2 = __half22float2(hp[2]);
            float2 f3 = __half22float2(hp[3]);
            float a0 = f0.x * cv, a1 = f0.y * cv, a2 = f1.x * cv, a3 = f1.y * cv;
            float a4 = f2.x * cv, a5 = f2.y * cv, a6 = f3.x * cv, a7 = f3.y * cv;
            __stcs((float4*)(sc + gofs),     make_float4(a0, a1, a2, a3));
            __stcs((float4*)(sc + gofs + 4), make_float4(a4, a5, a6, a7));
            __half2 s01 = __floats2half2_rn(a0, a1);
            __half2 s23 = __floats2half2_rn(a2, a3);
            __half2 s45 = __floats2half2_rn(a4, a5);
            __half2 s67 = __floats2half2_rn(a6, a7);
            uint4 sp;
            sp.x = *(uint32_t*)&s01; sp.y = *(uint32_t*)&s23;
            sp.z = *(uint32_t*)&s45; sp.w = *(uint32_t*)&s67;
            *(uint4*)&Ph[r][c8] = sp;
        }
        __syncthreads();   // Ph visible
#pragma unroll
        for (int kb = 0; kb < 64; kb += 16) {
            uint32_t a0, a1, a2, a3, a4, a5, a6, a7;
            ldsm4(a0, a1, a2, a3, aP0 + kb * 2);
            ldsm4(a4, a5, a6, a7, aP1 + kb * 2);
#pragma unroll
            for (int p = 0; p < 4; p++) {
                uint32_t h0, h1, h2, h3;
                ldsm4(h0, h1, h2, h3, bV + p * PSTRIDE + kb * 2);
                mma16816(acc[0][2 * p],     a0, a1, a2, a3, h0, h1);
                mma16816(acc[0][2 * p + 1], a0, a1, a2, a3, h2, h3);
                mma16816(acc[1][2 * p],     a4, a5, a6, a7, h0, h1);
                mma16816(acc[1][2 * p + 1], a4, a5, a6, a7, h2, h3);
            }
        }
    }
#pragma unroll
    for (int mt = 0; mt < 2; mt++) {
        const int rA = wid * 32 + mt * 16 + g, rB = rA + 8;
#pragma unroll
        for (int nt = 0; nt < 8; nt++) {
            const int c = h * DD + nt * 8 + 2 * tg;
            size_t iA = ((size_t)b * SD + q0 + rA) * ED + c;
            size_t iB = ((size_t)b * SD + q0 + rB) * ED + c;
            split_st(&g_ctxh[iA], &g_ctxl[iA], acc[mt][nt][0], acc[mt][nt][1]);
            split_st(&g_ctxh[iB], &g_ctxl[iB], acc[mt][nt][2], acc[mt][nt][3]);
        }
    }
}

// ---------------- LayerNorm ------------------------------------------------------
__global__ __launch_bounds__(256) void ln_kernel(
    const float* __restrict__ gamma, const float* __restrict__ beta,
    float* __restrict__ out)
{
    const int row = blockIdx.x;
    const int t = threadIdx.x;
    float4 v = *(const float4*)(g_tmp + (size_t)row * ED + t * 4);
    float s  = v.x + v.y + v.z + v.w;
    float s2 = v.x * v.x + v.y * v.y + v.z * v.z + v.w * v.w;
#pragma unroll
    for (int o = 16; o > 0; o >>= 1) {
        s  += __shfl_xor_sync(0xffffffffu, s, o);
        s2 += __shfl_xor_sync(0xffffffffu, s2, o);
    }
    __shared__ float ws[8], ws2[8];
    if ((t & 31) == 0) { ws[t >> 5] = s; ws2[t >> 5] = s2; }
    __syncthreads();
    if (t < 32) {
        float a = (t < 8) ? ws[t] : 0.f;
        float b = (t < 8) ? ws2[t] : 0.f;
#pragma unroll
        for (int o = 4; o > 0; o >>= 1) {
            a += __shfl_xor_sync(0xffffffffu, a, o);
            b += __shfl_xor_sync(0xffffffffu, b, o);
        }
        if (t == 0) { ws[0] = a; ws2[0] = b; }
    }
    __syncthreads();
    const float mu  = ws[0] * (1.f / ED);
    const float var = ws2[0] * (1.f / ED) - mu * mu;
    const float inv = rsqrtf(var + 1e-5f);
    const int c = t * 4;
    float4 ga = *(const float4*)(gamma + c);
    float4 be = *(const float4*)(beta + c);
    float4 o4;
    o4.x = (v.x - mu) * inv * ga.x + be.x;
    o4.y = (v.y - mu) * inv * ga.y + be.y;
    o4.z = (v.z - mu) * inv * ga.z + be.z;
    o4.w = (v.w - mu) * inv * ga.w + be.w;
    *(float4*)(out + (size_t)row * ED + c) = o4;
}

// ---------------- launch ---------------------------------------------------------
extern "C" void kernel_launch(void* const* d_in, const int* in_sizes, int n_in,
                              void* d_out, int out_size)
{
    const float* x     = (const float*)d_in[0];
    const float* Wq    = (const float*)d_in[1];
    const float* bq    = (const float*)d_in[2];
    const float* Wk    = (const float*)d_in[3];
    const float* bk    = (const float*)d_in[4];
    const float* Wv    = (const float*)d_in[5];
    const float* bv    = (const float*)d_in[6];
    const float* M     = (const float*)d_in[7];
    const float* Wo    = (const float*)d_in[8];
    const float* bo    = (const float*)d_in[9];
    const float* gamma = (const float*)d_in[10];
    const float* beta  = (const float*)d_in[11];

    float* outp  = (float*)d_out;
    float* attnp = outp + (size_t)ROWS * ED;   // tuple order: out, then attn

    cudaFuncSetAttribute(scores_mma,
                         cudaFuncAttributeMaxDynamicSharedMemorySize, (int)SC_SMEM);
    cudaFuncSetAttribute(qm_mma,
                         cudaFuncAttributeMaxDynamicSharedMemorySize, (int)QM_SMEM);
    cudaFuncSetAttribute(attn_ctx_mma,
                         cudaFuncAttributeMaxDynamicSharedMemorySize, (int)AC_SMEM);

    dim3 gProj(ED / 128, ROWS / 128);            // (8, 32)
    dim3 gProjQK(ED / 128, ROWS / 128, 2);       // (8, 32, 2)

    prep_kernel<<<(N4X + 4 * N4W) / 256, 256>>>(x, Wq, Wk, Wv, Wo);   // idx 0
    hgemm_qk<<<gProjQK, 256>>>(bq, bk);                               // idx 1
    qm_mma<<<dim3(BHS / 128, 2), 256, QM_SMEM>>>(M);                  // idx 2
    scores_mma<<<dim3(SD / 256, BH), 256, SC_SMEM>>>();               // idx 3  <- profiled
    hgemm_v<<<gProj, 256>>>(bv);                                      // idx 4
    attn_ctx_mma<<<dim3(SD / 256, BH), 256, AC_SMEM>>>(attnp);        // idx 5
    hgemm_o<<<gProj, 256>>>(bo, x);                                   // idx 6
    ln_kernel<<<ROWS, 256>>>(gamma, beta, outp);                      // idx 7
}

// round 14
// speedup vs baseline: 1.2287x; 1.0884x over previous
#include <cuda_runtime.h>
#include <cuda_fp16.h>
#include <math.h>
#include <stdint.h>

#define SD 2048
#define ED 1024
#define HD 16
#define DD 64
#define BD 2
#define BH (BD*HD)     /* 32 */
#define ROWS (BD*SD)   /* 4096 */
#define BHS (BH*SD)    /* 65536 */

#define C1 11.5415603f   /* 8*log2(e) */
#define C2 23.0831206f   /* 16*log2(e) */

#define N4X (ROWS * ED / 4)   /* 1048576 */
#define N4W (ED * ED / 4)     /*  262144 */

// ---------------- scratch ----------------
__device__ __half g_xh[(size_t)ROWS * ED];
__device__ __half g_xl[(size_t)ROWS * ED];
__device__ __half g_wqh[(size_t)ED * ED];
__device__ __half g_wql[(size_t)ED * ED];
__device__ __half g_wkh[(size_t)ED * ED];
__device__ __half g_wkl[(size_t)ED * ED];
__device__ __half g_wvh[(size_t)ED * ED];
__device__ __half g_woh[(size_t)ED * ED];
__device__ __half g_Qh[(size_t)BHS * DD];
__device__ __half g_Ql[(size_t)BHS * DD];
__device__ __half g_Kh[(size_t)BHS * DD];
__device__ __half g_Kl[(size_t)BHS * DD];
__device__ __half g_Vh[(size_t)BHS * DD];
__device__ __half g_qMh[(size_t)BHS * DD];
__device__ __half g_qMl[(size_t)BHS * DD];
__device__ float  g_qMq[BHS];
__device__ float  g_kMk[BHS];
__device__ float  g_rowm[BHS];
__device__ float  g_rowl[BHS];
__device__ float  g_blkm[(size_t)32 * BHS];      /* [blk][bh*SD+row] transposed */
__device__ __half g_P[(size_t)BH * SD * SD];     /* 268 MB: unnormalized probs fp16 */
__device__ __half g_ctxh[(size_t)ROWS * ED];
__device__ __half g_ctxl[(size_t)ROWS * ED];
__device__ float  g_tmp[(size_t)ROWS * ED];

// ---------------- helpers ----------------
__device__ __forceinline__ float ex2(float x) {
    float y; asm("ex2.approx.f32 %0, %1;" : "=f"(y) : "f"(x)); return y;
}

__device__ __forceinline__ void mma16816(float (&c)[4],
    uint32_t a0, uint32_t a1, uint32_t a2, uint32_t a3, uint32_t b0, uint32_t b1)
{
    asm volatile(
        "mma.sync.aligned.m16n8k16.row.col.f32.f16.f16.f32 "
        "{%0,%1,%2,%3}, {%4,%5,%6,%7}, {%8,%9}, {%0,%1,%2,%3};"
        : "+f"(c[0]), "+f"(c[1]), "+f"(c[2]), "+f"(c[3])
        : "r"(a0), "r"(a1), "r"(a2), "r"(a3), "r"(b0), "r"(b1));
}

__device__ __forceinline__ void ldsm4(uint32_t& r0, uint32_t& r1, uint32_t& r2, uint32_t& r3,
                                      uint32_t addr)
{
    asm volatile("ldmatrix.sync.aligned.m8n8.x4.shared.b16 {%0,%1,%2,%3}, [%4];"
        : "=r"(r0), "=r"(r1), "=r"(r2), "=r"(r3) : "r"(addr));
}

__device__ __forceinline__ uint32_t ld_u32(const __half* p) {
    return *reinterpret_cast<const uint32_t*>(p);
}

__device__ __forceinline__ void split_st(__half* ph, __half* pl, float x, float y) {
    __half hx = __float2half_rn(x), hy = __float2half_rn(y);
    *reinterpret_cast<__half2*>(ph) = __halves2half2(hx, hy);
    __half lx = __float2half_rn(x - __half2float(hx));
    __half ly = __float2half_rn(y - __half2float(hy));
    *reinterpret_cast<__half2*>(pl) = __halves2half2(lx, ly);
}

// ---------------- fused converter ----------------
__global__ __launch_bounds__(256) void prep_kernel(
    const float* __restrict__ x,
    const float* __restrict__ Wq, const float* __restrict__ Wk,
    const float* __restrict__ Wv, const float* __restrict__ Wo)
{
    int i = blockIdx.x * 256 + threadIdx.x;
    if (i < N4X) {
        float4 v = ((const float4*)x)[i];
        split_st(g_xh + 4 * (size_t)i,     g_xl + 4 * (size_t)i,     v.x, v.y);
        split_st(g_xh + 4 * (size_t)i + 2, g_xl + 4 * (size_t)i + 2, v.z, v.w);
        return;
    }
    int j = i - N4X;
    int w = j / N4W, o = j % N4W;
    if (w == 0) {
        float4 v = ((const float4*)Wq)[o];
        split_st(g_wqh + 4 * (size_t)o,     g_wql + 4 * (size_t)o,     v.x, v.y);
        split_st(g_wqh + 4 * (size_t)o + 2, g_wql + 4 * (size_t)o + 2, v.z, v.w);
    } else if (w == 1) {
        float4 v = ((const float4*)Wk)[o];
        split_st(g_wkh + 4 * (size_t)o,     g_wkl + 4 * (size_t)o,     v.x, v.y);
        split_st(g_wkh + 4 * (size_t)o + 2, g_wkl + 4 * (size_t)o + 2, v.z, v.w);
    } else if (w == 2) {
        float4 v = ((const float4*)Wv)[o];
        __half2* d = (__half2*)(g_wvh + 4 * (size_t)o);
        d[0] = __floats2half2_rn(v.x, v.y);
        d[1] = __floats2half2_rn(v.z, v.w);
    } else {
        float4 v = ((const float4*)Wo)[o];
        __half2* d = (__half2*)(g_woh + 4 * (size_t)o);
        d[0] = __floats2half2_rn(v.x, v.y);
        d[1] = __floats2half2_rn(v.z, v.w);
    }
}

// ---------------- 128x128 HGEMM core (ldmatrix inner loop) ----------------
// NSPLIT: 3 = AhBh+AhBl+AlBh, 2 = AhBh+AlBh, 1 = AhBh
// MODE 2 (V): fp16 (hi only) scatter +bias
// MODE 3 (O): fp32 row-major + bias + resid
// MODE 4 (Q/K): split fp16 scatter +bias
template <int MODE, int NSPLIT>
__device__ __forceinline__ void hgemm_core(
    char* smem,
    const __half* __restrict__ Ahg, const __half* __restrict__ Alg,
    const __half* __restrict__ Bhg, const __half* __restrict__ Blg,
    float* __restrict__ C, __half* __restrict__ Ch, __half* __restrict__ Cl,
    const float* __restrict__ bias, const float* __restrict__ resid)
{
    __half (*Ah)[40] = (__half(*)[40])smem;
    __half (*Bh)[40] = Ah + 128;
    __half (*Al)[40] = Ah + 256;
    __half (*Bl)[40] = Ah + 384;   // only allocated when NSPLIT >= 3
    const int t = threadIdx.x;
    const int wid = t >> 5, lane = t & 31;
    const int g = lane >> 2, tg = lane & 3;
    const int wr = wid >> 1, wc = wid & 1;
    const int row0 = blockIdx.y * 128, col0 = blockIdx.x * 128;
    const int lr = t >> 1, lq = (t & 1) * 16;
    const __half* Aph = Ahg + (size_t)(row0 + lr) * ED + lq;
    const __half* Apl = (NSPLIT >= 2) ? Alg + (size_t)(row0 + lr) * ED + lq : nullptr;
    const __half* Bph = Bhg + (size_t)(col0 + lr) * ED + lq;
    const __half* Bpl = (NSPLIT >= 3) ? Blg + (size_t)(col0 + lr) * ED + lq : nullptr;

    // ldmatrix lane addressing
    const int aRow = wr * 32 + (lane & 15), aCol = (lane >> 4) * 8;
    const int bRow = wc * 64 + ((lane >> 4) * 8) + (lane & 7);
    const int bCol = ((lane >> 3) & 1) * 8;
    const uint32_t ROWB = 40 * 2;          // bytes per smem row
    const uint32_t MTS  = 16 * ROWB;       // 16-row stride (m-tile / n-tile pair)
    const uint32_t aH0 = (uint32_t)__cvta_generic_to_shared(&Ah[aRow][aCol]);
    const uint32_t aL0 = (NSPLIT >= 2) ? (uint32_t)__cvta_generic_to_shared(&Al[aRow][aCol]) : 0;
    const uint32_t bH0 = (uint32_t)__cvta_generic_to_shared(&Bh[bRow][bCol]);
    const uint32_t bL0 = (NSPLIT >= 3) ? (uint32_t)__cvta_generic_to_shared(&Bl[bRow][bCol]) : 0;

    float acc[2][8][4];
#pragma unroll
    for (int mt = 0; mt < 2; mt++)
#pragma unroll
        for (int nt = 0; nt < 8; nt++)
#pragma unroll
            for (int j = 0; j < 4; j++) acc[mt][nt][j] = 0.f;

    uint4 va0 = *(const uint4*)(Aph),  va1 = *(const uint4*)(Aph + 8);
    uint4 vb0 = *(const uint4*)(Bph),  vb1 = *(const uint4*)(Bph + 8);
    uint4 vl0, vl1, vm0, vm1;
    if (NSPLIT >= 2) { vl0 = *(const uint4*)(Apl); vl1 = *(const uint4*)(Apl + 8); }
    if (NSPLIT >= 3) { vm0 = *(const uint4*)(Bpl); vm1 = *(const uint4*)(Bpl + 8); }

    for (int k0 = 0; k0 < ED; k0 += 32) {
        *(uint4*)&Ah[lr][lq] = va0; *(uint4*)&Ah[lr][lq + 8] = va1;
        *(uint4*)&Bh[lr][lq] = vb0; *(uint4*)&Bh[lr][lq + 8] = vb1;
        if (NSPLIT >= 2) { *(uint4*)&Al[lr][lq] = vl0; *(uint4*)&Al[lr][lq + 8] = vl1; }
        if (NSPLIT >= 3) { *(uint4*)&Bl[lr][lq] = vm0; *(uint4*)&Bl[lr][lq + 8] = vm1; }
        __syncthreads();
        if (k0 + 32 < ED) {
            va0 = *(const uint4*)(Aph + k0 + 32); va1 = *(const uint4*)(Aph + k0 + 40);
            vb0 = *(const uint4*)(Bph + k0 + 32); vb1 = *(const uint4*)(Bph + k0 + 40);
            if (NSPLIT >= 2) { vl0 = *(const uint4*)(Apl + k0 + 32); vl1 = *(const uint4*)(Apl + k0 + 40); }
            if (NSPLIT >= 3) { vm0 = *(const uint4*)(Bpl + k0 + 32); vm1 = *(const uint4*)(Bpl + k0 + 40); }
        }
#pragma unroll
        for (int ks = 0; ks < 2; ks++) {
            const uint32_t kb2 = (uint32_t)(ks * 16 * 2);
            uint32_t ah[2][4], al[2][4];
            ldsm4(ah[0][0], ah[0][1], ah[0][2], ah[0][3], aH0 + kb2);
            ldsm4(ah[1][0], ah[1][1], ah[1][2], ah[1][3], aH0 + MTS + kb2);
            if (NSPLIT >= 2) {
                ldsm4(al[0][0], al[0][1], al[0][2], al[0][3], aL0 + kb2);
                ldsm4(al[1][0], al[1][1], al[1][2], al[1][3], aL0 + MTS + kb2);
            }
#pragma unroll
            for (int p = 0; p < 4; p++) {
                uint32_t h0, h1, h2, h3;
                ldsm4(h0, h1, h2, h3, bH0 + p * MTS + kb2);
                uint32_t l0, l1, l2, l3;
                if (NSPLIT >= 3) ldsm4(l0, l1, l2, l3, bL0 + p * MTS + kb2);
#pragma unroll
                for (int mt = 0; mt < 2; mt++) {
                    mma16816(acc[mt][2 * p], ah[mt][0], ah[mt][1], ah[mt][2], ah[mt][3], h0, h1);
                    if (NSPLIT >= 3)
                        mma16816(acc[mt][2 * p], ah[mt][0], ah[mt][1], ah[mt][2], ah[mt][3], l0, l1);
                    if (NSPLIT >= 2)
                        mma16816(acc[mt][2 * p], al[mt][0], al[mt][1], al[mt][2], al[mt][3], h0, h1);
                    mma16816(acc[mt][2 * p + 1], ah[mt][0], ah[mt][1], ah[mt][2], ah[mt][3], h2, h3);
                    if (NSPLIT >= 3)
                        mma16816(acc[mt][2 * p + 1], ah[mt][0], ah[mt][1], ah[mt][2], ah[mt][3], l2, l3);
                    if (NSPLIT >= 2)
                        mma16816(acc[mt][2 * p + 1], al[mt][0], al[mt][1], al[mt][2], al[mt][3], h2, h3);
                }
            }
        }
        __syncthreads();
    }

#pragma unroll
    for (int mt = 0; mt < 2; mt++) {
        const int rA = row0 + wr * 32 + mt * 16 + g;
        const int rB = rA + 8;
#pragma unroll
        for (int nt = 0; nt < 8; nt++) {
            const int c = col0 + wc * 64 + nt * 8 + 2 * tg;
            const float b0 = bias[c], b1 = bias[c + 1];
            float v00 = acc[mt][nt][0] + b0, v01 = acc[mt][nt][1] + b1;
            float v10 = acc[mt][nt][2] + b0, v11 = acc[mt][nt][3] + b1;
            if (MODE == 3) {
                size_t iA = (size_t)rA * ED + c;
                size_t iB = (size_t)rB * ED + c;
                float2 r0 = *(const float2*)&resid[iA];
                float2 r1 = *(const float2*)&resid[iB];
                *(float2*)&C[iA] = make_float2(v00 + r0.x, v01 + r0.y);
                *(float2*)&C[iB] = make_float2(v10 + r1.x, v11 + r1.y);
            } else {
                const int h_ = c >> 6, d_ = c & 63;
                size_t iA = (((size_t)(rA >> 11) * HD + h_) * SD + (rA & (SD - 1))) * DD + d_;
                size_t iB = (((size_t)(rB >> 11) * HD + h_) * SD + (rB & (SD - 1))) * DD + d_;
                if (MODE == 4) {
                    split_st(&Ch[iA], &Cl[iA], v00, v01);
                    split_st(&Ch[iB], &Cl[iB], v10, v11);
                }
                if (MODE == 2) {
                    *(__half2*)&Ch[iA] = __floats2half2_rn(v00, v01);
                    *(__half2*)&Ch[iB] = __floats2half2_rn(v10, v11);
                }
            }
        }
    }
}

// Q/K projections: x2 split (AhBh + AlBh) — weight-lo term dropped (error ~1e-4 rel)
__global__ __launch_bounds__(256) void hgemm_qk(
    const float* __restrict__ bq, const float* __restrict__ bk)
{
    __shared__ char smem[3 * 128 * 40 * 2];
    if (blockIdx.z == 0)
        hgemm_core<4, 2>(smem, g_xh, g_xl, g_wqh, nullptr, nullptr, g_Qh, g_Ql, bq, nullptr);
    else
        hgemm_core<4, 2>(smem, g_xh, g_xl, g_wkh, nullptr, nullptr, g_Kh, g_Kl, bk, nullptr);
}

__global__ __launch_bounds__(256) void hgemm_v(const float* __restrict__ bv)
{
    __shared__ char smem[2 * 128 * 40 * 2];
    hgemm_core<2, 1>(smem, g_xh, nullptr, g_wvh, nullptr, nullptr, g_Vh, nullptr, bv, nullptr);
}

__global__ __launch_bounds__(256) void hgemm_o(
    const float* __restrict__ bo, const float* __restrict__ resid)
{
    __shared__ char smem[3 * 128 * 40 * 2];
    hgemm_core<3, 2>(smem, g_ctxh, g_ctxl, g_woh, nullptr, g_tmp, nullptr, nullptr, bo, resid);
}

// ---------------- qm via mma (unchanged) ----------------
#define QM_SMEM (size_t)((128 + 128 + 64 + 64) * 72 * 2)
__global__ __launch_bounds__(256) void qm_mma(const float* __restrict__ M)
{
    extern __shared__ __half qsm[];
    __half (*Qh_s)[72] = (__half(*)[72])qsm;
    __half (*Ql_s)[72] = Qh_s + 128;
    __half (*Mh_s)[72] = Qh_s + 256;
    __half (*Ml_s)[72] = Qh_s + 320;
    const int t = threadIdx.x, wid = t >> 5, lane = t & 31;
    const int g = lane >> 2, tg = lane & 3;
    const int r0 = blockIdx.x * 128;
    const bool isQ = (blockIdx.y == 0);
    const __half* Ahg = isQ ? g_Qh : g_Kh;
    const __half* Alg = isQ ? g_Ql : g_Kl;

    for (int idx = t; idx < 64 * 64; idx += 256) {
        int d = idx >> 6, e = idx & 63;
        float v = M[d * 64 + e];
        __half hv = __float2half_rn(v);
        Mh_s[e][d] = hv;
        Ml_s[e][d] = __float2half_rn(v - __half2float(hv));
    }
    for (int idx = t; idx < 128 * 8; idx += 256) {
        int r = idx >> 3, c8 = (idx & 7) * 8;
        *(uint4*)&Qh_s[r][c8] = *(const uint4*)(Ahg + (size_t)(r0 + r) * DD + c8);
        *(uint4*)&Ql_s[r][c8] = *(const uint4*)(Alg + (size_t)(r0 + r) * DD + c8);
    }
    __syncthreads();

    const int rA = wid * 16 + g, rB = rA + 8;
    float acc[8][4];
#pragma unroll
    for (int nt = 0; nt < 8; nt++)
#pragma unroll
        for (int j = 0; j < 4; j++) acc[nt][j] = 0.f;

#pragma unroll
    for (int kb = 0; kb < 64; kb += 16) {
        uint32_t ah0 = ld_u32(&Qh_s[rA][kb + 2 * tg]);
        uint32_t ah1 = ld_u32(&Qh_s[rB][kb + 2 * tg]);
        uint32_t ah2 = ld_u32(&Qh_s[rA][kb + 2 * tg + 8]);
        uint32_t ah3 = ld_u32(&Qh_s[rB][kb + 2 * tg + 8]);
        uint32_t al0 = ld_u32(&Ql_s[rA][kb + 2 * tg]);
        uint32_t al1 = ld_u32(&Ql_s[rB][kb + 2 * tg]);
        uint32_t al2 = ld_u32(&Ql_s[rA][kb + 2 * tg + 8]);
        uint32_t al3 = ld_u32(&Ql_s[rB][kb + 2 * tg + 8]);
#pragma unroll
        for (int nt = 0; nt < 8; nt++) {
            const int nr = nt * 8 + g;
            uint32_t bh0 = ld_u32(&Mh_s[nr][kb + 2 * tg]);
            uint32_t bh1 = ld_u32(&Mh_s[nr][kb + 2 * tg + 8]);
            uint32_t bl0 = ld_u32(&Ml_s[nr][kb + 2 * tg]);
            uint32_t bl1 = ld_u32(&Ml_s[nr][kb + 2 * tg + 8]);
            mma16816(acc[nt], ah0, ah1, ah2, ah3, bh0, bh1);
            mma16816(acc[nt], ah0, ah1, ah2, ah3, bl0, bl1);
            mma16816(acc[nt], al0, al1, al2, al3, bh0, bh1);
        }
    }

    float dotA = 0.f, dotB = 0.f;
#pragma unroll
    for (int nt = 0; nt < 8; nt++) {
        const int c0 = nt * 8 + 2 * tg;
        if (isQ) {
            split_st(&g_qMh[(size_t)(r0 + rA) * DD + c0], &g_qMl[(size_t)(r0 + rA) * DD + c0],
                     acc[nt][0], acc[nt][1]);
            split_st(&g_qMh[(size_t)(r0 + rB) * DD + c0], &g_qMl[(size_t)(r0 + rB) * DD + c0],
                     acc[nt][2], acc[nt][3]);
        }
        float qA0 = __half2float(Qh_s[rA][c0])     + __half2float(Ql_s[rA][c0]);
        float qA1 = __half2float(Qh_s[rA][c0 + 1]) + __half2float(Ql_s[rA][c0 + 1]);
        float qB0 = __half2float(Qh_s[rB][c0])     + __half2float(Ql_s[rB][c0]);
        float qB1 = __half2float(Qh_s[rB][c0 + 1]) + __half2float(Ql_s[rB][c0 + 1]);
        dotA = fmaf(acc[nt][0], qA0, fmaf(acc[nt][1], qA1, dotA));
        dotB = fmaf(acc[nt][2], qB0, fmaf(acc[nt][3], qB1, dotB));
    }
    dotA += __shfl_xor_sync(0xffffffffu, dotA, 1);
    dotA += __shfl_xor_sync(0xffffffffu, dotA, 2);
    dotB += __shfl_xor_sync(0xffffffffu, dotB, 1);
    dotB += __shfl_xor_sync(0xffffffffu, dotB, 2);
    if (tg == 0) {
        float* dst = isQ ? g_qMq : g_kMk;
        dst[r0 + rA] = dotA;
        dst[r0 + rB] = dotB;
    }
}

// ---------------- pass 1: 256 q-rows x 64 k-cols per iter (unchanged) -----------
#define SC_SMEM (size_t)((256 + 256 + 64 + 64) * 72 * 2)   /* 92160 B */
__global__ __launch_bounds__(256) void scores_mma()
{
    extern __shared__ __half smx[];
    __half (*qMh)[72] = (__half(*)[72])smx;       // [256][72]
    __half (*qMl)[72] = qMh + 256;                // [256][72]
    __half (*Kh)[72]  = qMh + 512;                // [64][72]
    __half (*Kl)[72]  = qMh + 576;                // [64][72]
    __shared__ float qq[256], kks[64];

    const int bh = blockIdx.y, q0 = blockIdx.x * 256;
    const __half* qMhb = g_qMh + (size_t)bh * SD * DD;
    const __half* qMlb = g_qMl + (size_t)bh * SD * DD;
    const __half* Khb  = g_Kh  + (size_t)bh * SD * DD;
    const __half* Klb  = g_Kl  + (size_t)bh * SD * DD;
    __half* Pb = g_P + (size_t)bh * SD * SD;
    const int t = threadIdx.x, wid = t >> 5, lane = t & 31;
    const int g = lane >> 2, tg = lane & 3;

    const int aR = wid * 32 + (lane & 15), aC = (lane >> 4) * 8;
    const int bRow = ((lane >> 4) * 8) + (lane & 7);
    const int bCol = ((lane >> 3) & 1) * 8;
    const uint32_t aH0 = (uint32_t)__cvta_generic_to_shared(&qMh[aR][aC]);
    const uint32_t aH1 = (uint32_t)__cvta_generic_to_shared(&qMh[aR + 16][aC]);
    const uint32_t aL0 = (uint32_t)__cvta_generic_to_shared(&qMl[aR][aC]);
    const uint32_t aL1 = (uint32_t)__cvta_generic_to_shared(&qMl[aR + 16][aC]);
    const uint32_t bHb = (uint32_t)__cvta_generic_to_shared(&Kh[bRow][bCol]);
    const uint32_t bLb = (uint32_t)__cvta_generic_to_shared(&Kl[bRow][bCol]);
    const uint32_t PSTRIDE = 16 * 72 * 2;

    for (int idx = t; idx < 256 * 8; idx += 256) {
        int r = idx >> 3, c8 = (idx & 7) * 8;
        *(uint4*)&qMh[r][c8] = *(const uint4*)(qMhb + (size_t)(q0 + r) * DD + c8);
        *(uint4*)&qMl[r][c8] = *(const uint4*)(qMlb + (size_t)(q0 + r) * DD + c8);
    }
    qq[t] = C1 * g_qMq[bh * SD + q0 + t];

    float mr[4] = {-1e30f, -1e30f, -1e30f, -1e30f};
    float lr[4] = {0.f, 0.f, 0.f, 0.f};

    for (int n0 = 0; n0 < SD; n0 += 64) {
        __syncthreads();
        for (int idx = t; idx < 64 * 8; idx += 256) {
            int r = idx >> 3, c8 = (idx & 7) * 8;
            *(uint4*)&Kh[r][c8] = *(const uint4*)(Khb + (size_t)(n0 + r) * DD + c8);
            *(uint4*)&Kl[r][c8] = *(const uint4*)(Klb + (size_t)(n0 + r) * DD + c8);
        }
        if (t < 64) kks[t] = C1 * g_kMk[bh * SD + n0 + t];
        __syncthreads();

        float acc[2][8][4];
#pragma unroll
        for (int mt = 0; mt < 2; mt++)
#pragma unroll
            for (int nt = 0; nt < 8; nt++)
#pragma unroll
                for (int j = 0; j < 4; j++) acc[mt][nt][j] = 0.f;

#pragma unroll
        for (int kb = 0; kb < 64; kb += 16) {
            uint32_t ah[2][4], al[2][4];
            ldsm4(ah[0][0], ah[0][1], ah[0][2], ah[0][3], aH0 + kb * 2);
            ldsm4(ah[1][0], ah[1][1], ah[1][2], ah[1][3], aH1 + kb * 2);
            ldsm4(al[0][0], al[0][1], al[0][2], al[0][3], aL0 + kb * 2);
            ldsm4(al[1][0], al[1][1], al[1][2], al[1][3], aL1 + kb * 2);
#pragma unroll
            for (int p = 0; p < 4; p++) {
                uint32_t h0, h1, h2, h3, l0, l1, l2, l3;
                ldsm4(h0, h1, h2, h3, bHb + p * PSTRIDE + kb * 2);
                ldsm4(l0, l1, l2, l3, bLb + p * PSTRIDE + kb * 2);
#pragma unroll
                for (int mt = 0; mt < 2; mt++) {
                    mma16816(acc[mt][2 * p],     ah[mt][0], ah[mt][1], ah[mt][2], ah[mt][3], h0, h1);
                    mma16816(acc[mt][2 * p],     ah[mt][0], ah[mt][1], ah[mt][2], ah[mt][3], l0, l1);
                    mma16816(acc[mt][2 * p],     al[mt][0], al[mt][1], al[mt][2], al[mt][3], h0, h1);
                    mma16816(acc[mt][2 * p + 1], ah[mt][0], ah[mt][1], ah[mt][2], ah[mt][3], h2, h3);
                    mma16816(acc[mt][2 * p + 1], ah[mt][0], ah[mt][1], ah[mt][2], ah[mt][3], l2, l3);
                    mma16816(acc[mt][2 * p + 1], al[mt][0], al[mt][1], al[mt][2], al[mt][3], h2, h3);
                }
            }
        }

#pragma unroll
        for (int mt = 0; mt < 2; mt++) {
            const int rA = wid * 32 + mt * 16 + g, rB = rA + 8;
            const float qA = qq[rA], qB = qq[rB];
            float mA = -1e30f, mB = -1e30f;
#pragma unroll
            for (int nt = 0; nt < 8; nt++) {
                const float k0v = kks[nt * 8 + 2 * tg], k1v = kks[nt * 8 + 2 * tg + 1];
                float s0 = fmaf(C2, acc[mt][nt][0], -qA) - k0v;
                float s1 = fmaf(C2, acc[mt][nt][1], -qA) - k1v;
                float s2 = fmaf(C2, acc[mt][nt][2], -qB) - k0v;
                float s3 = fmaf(C2, acc[mt][nt][3], -qB) - k1v;
                acc[mt][nt][0] = s0; acc[mt][nt][1] = s1;
                acc[mt][nt][2] = s2; acc[mt][nt][3] = s3;
                mA = fmaxf(mA, fmaxf(s0, s1));
                mB = fmaxf(mB, fmaxf(s2, s3));
            }
            mA = fmaxf(mA, __shfl_xor_sync(0xffffffffu, mA, 1));
            mA = fmaxf(mA, __shfl_xor_sync(0xffffffffu, mA, 2));
            mB = fmaxf(mB, __shfl_xor_sync(0xffffffffu, mB, 1));
            mB = fmaxf(mB, __shfl_xor_sync(0xffffffffu, mB, 2));

            float SA = 0.f, SB = 0.f;
#pragma unroll
            for (int nt = 0; nt < 8; nt++) {
                float p0 = ex2(acc[mt][nt][0] - mA);
                float p1 = ex2(acc[mt][nt][1] - mA);
                float p2 = ex2(acc[mt][nt][2] - mB);
                float p3 = ex2(acc[mt][nt][3] - mB);
                __half2 hA = __floats2half2_rn(p0, p1);
                __half2 hB = __floats2half2_rn(p2, p3);
                __stcs((unsigned int*)(Pb + (size_t)(q0 + rA) * SD + n0 + nt * 8 + 2 * tg),
                       *(unsigned int*)&hA);
                __stcs((unsigned int*)(Pb + (size_t)(q0 + rB) * SD + n0 + nt * 8 + 2 * tg),
                       *(unsigned int*)&hB);
                SA += p0 + p1;
                SB += p2 + p3;
            }
            SA += __shfl_xor_sync(0xffffffffu, SA, 1);
            SA += __shfl_xor_sync(0xffffffffu, SA, 2);
            SB += __shfl_xor_sync(0xffffffffu, SB, 1);
            SB += __shfl_xor_sync(0xffffffffu, SB, 2);

            if (tg == 0) {
                g_blkm[(size_t)(n0 >> 6) * BHS + bh * SD + q0 + rA] = mA;
                g_blkm[(size_t)(n0 >> 6) * BHS + bh * SD + q0 + rB] = mB;
            }
            const int iA = 2 * mt, iB = 2 * mt + 1;
            float mnA = fmaxf(mr[iA], mA);
            lr[iA] = lr[iA] * ex2(mr[iA] - mnA) + SA * ex2(mA - mnA);
            mr[iA] = mnA;
            float mnB = fmaxf(mr[iB], mB);
            lr[iB] = lr[iB] * ex2(mr[iB] - mnB) + SB * ex2(mB - mnB);
            mr[iB] = mnB;
        }
    }
    if (tg == 0) {
#pragma unroll
        for (int mt = 0; mt < 2; mt++) {
            const int rA = wid * 32 + mt * 16 + g;
            g_rowm[bh * SD + q0 + rA]     = mr[2 * mt];
            g_rowl[bh * SD + q0 + rA]     = lr[2 * mt];
            g_rowm[bh * SD + q0 + rA + 8] = mr[2 * mt + 1];
            g_rowl[bh * SD + q0 + rA + 8] = lr[2 * mt + 1];
        }
    }
}

// ---------------- pass 2: 256 rows/block; P scaled at staging (unchanged) -------
#define AC_SMEM (size_t)((256 + 64) * 72 * 2)   /* 46080 B */
__global__ __launch_bounds__(256) void attn_ctx_mma(float* __restrict__ attn)
{
    extern __shared__ __half acsm[];
    __half (*Ph)[72] = (__half(*)[72])acsm;   // [256][72] holds p*c (scaled)
    __half (*Vs)[72] = Ph + 256;              // [64][72]
    __shared__ float c_blk[256], rm_s[256], rli_s[256];
    const int bh = blockIdx.y, q0 = blockIdx.x * 256;
    const int b = bh >> 4, h = bh & 15;
    const __half* Pb = g_P + (size_t)bh * SD * SD;
    float* sc = attn + (size_t)bh * SD * SD;
    const __half* Vhb = g_Vh + (size_t)bh * SD * DD;
    const int t = threadIdx.x, wid = t >> 5, lane = t & 31;
    const int g = lane >> 2, tg = lane & 3;

    const int aRow = wid * 32 + (lane & 15), aCol = (lane >> 4) * 8;
    const int bRow = ((lane >> 4) * 8) + (lane & 7);
    const int bCol = ((lane >> 3) & 1) * 8;
    const uint32_t aP0 = (uint32_t)__cvta_generic_to_shared(&Ph[aRow][aCol]);
    const uint32_t aP1 = (uint32_t)__cvta_generic_to_shared(&Ph[aRow + 16][aCol]);
    const uint32_t bV  = (uint32_t)__cvta_generic_to_shared(&Vs[bRow][bCol]);
    const uint32_t PSTRIDE = 16 * 72 * 2;

    rm_s[t]  = g_rowm[bh * SD + q0 + t];
    rli_s[t] = 1.f / g_rowl[bh * SD + q0 + t];

    float acc[2][8][4];
#pragma unroll
    for (int mt = 0; mt < 2; mt++)
#pragma unroll
        for (int nt = 0; nt < 8; nt++)
#pragma unroll
            for (int j = 0; j < 4; j++) acc[mt][nt][j] = 0.f;

    for (int k0 = 0; k0 < SD; k0 += 64) {
        const int blk = k0 >> 6;
        __syncthreads();
        c_blk[t] = ex2(g_blkm[(size_t)blk * BHS + bh * SD + q0 + t] - rm_s[t]) * rli_s[t];
        for (int idx = t; idx < 512; idx += 256) {
            int r = idx >> 3, c8 = (idx & 7) * 8;
            uint4 rh = *(const uint4*)(Vhb + (size_t)(k0 + r) * DD + c8);
            const __half* hp = (const __half*)&rh;
#pragma unroll
            for (int j = 0; j < 8; j++) Vs[c8 + j][r] = hp[j];
        }
        __syncthreads();
        for (int idx = t; idx < 2048; idx += 256) {
            int r = idx >> 3, c8 = (idx & 7) * 8;
            size_t gofs = (size_t)(q0 + r) * SD + k0 + c8;
            uint4 pv = __ldcs((const uint4*)(Pb + gofs));
            const float cv = c_blk[r];
            const __half2* hp = (const __half2*)&pv;
            float2 f0 = __half22float2(hp[0]);
            float2 f1 = __half22float2(hp[1]);
            float2 f2 = __half22float2(hp[2]);
            float2 f3 = __half22float2(hp[3]);
            float a0 = f0.x * cv, a1 = f0.y * cv, a2 = f1.x * cv, a3 = f1.y * cv;
            float a4 = f2.x * cv, a5 = f2.y * cv, a6 = f3.x * cv, a7 = f3.y * cv;
            __stcs((float4*)(sc + gofs),     make_float4(a0, a1, a2, a3));
            __stcs((float4*)(sc + gofs + 4), make_float4(a4, a5, a6, a7));
            __half2 s01 = __floats2half2_rn(a0, a1);
            __half2 s23 = __floats2half2_rn(a2, a3);
            __half2 s45 = __floats2half2_rn(a4, a5);
            __half2 s67 = __floats2half2_rn(a6, a7);
            uint4 sp;
            sp.x = *(uint32_t*)&s01; sp.y = *(uint32_t*)&s23;
            sp.z = *(uint32_t*)&s45; sp.w = *(uint32_t*)&s67;
            *(uint4*)&Ph[r][c8] = sp;
        }
        __syncthreads();
#pragma unroll
        for (int kb = 0; kb < 64; kb += 16) {
            uint32_t a0, a1, a2, a3, a4, a5, a6, a7;
            ldsm4(a0, a1, a2, a3, aP0 + kb * 2);
            ldsm4(a4, a5, a6, a7, aP1 + kb * 2);
#pragma unroll
            for (int p = 0; p < 4; p++) {
                uint32_t h0, h1, h2, h3;
                ldsm4(h0, h1, h2, h3, bV + p * PSTRIDE + kb * 2);
                mma16816(acc[0][2 * p],     a0, a1, a2, a3, h0, h1);
                mma16816(acc[0][2 * p + 1], a0, a1, a2, a3, h2, h3);
                mma16816(acc[1][2 * p],     a4, a5, a6, a7, h0, h1);
                mma16816(acc[1][2 * p + 1], a4, a5, a6, a7, h2, h3);
            }
        }
    }
#pragma unroll
    for (int mt = 0; mt < 2; mt++) {
        const int rA = wid * 32 + mt * 16 + g, rB = rA + 8;
#pragma unroll
        for (int nt = 0; nt < 8; nt++) {
            const int c = h * DD + nt * 8 + 2 * tg;
            size_t iA = ((size_t)b * SD + q0 + rA) * ED + c;
            size_t iB = ((size_t)b * SD + q0 + rB) * ED + c;
            split_st(&g_ctxh[iA], &g_ctxl[iA], acc[mt][nt][0], acc[mt][nt][1]);
            split_st(&g_ctxh[iB], &g_ctxl[iB], acc[mt][nt][2], acc[mt][nt][3]);
        }
    }
}

// ---------------- LayerNorm ------------------------------------------------------
__global__ __launch_bounds__(256) void ln_kernel(
    const float* __restrict__ gamma, const float* __restrict__ beta,
    float* __restrict__ out)
{
    const int row = blockIdx.x;
    const int t = threadIdx.x;
    float4 v = *(const float4*)(g_tmp + (size_t)row * ED + t * 4);
    float s  = v.x + v.y + v.z + v.w;
    float s2 = v.x * v.x + v.y * v.y + v.z * v.z + v.w * v.w;
#pragma unroll
    for (int o = 16; o > 0; o >>= 1) {
        s  += __shfl_xor_sync(0xffffffffu, s, o);
        s2 += __shfl_xor_sync(0xffffffffu, s2, o);
    }
    __shared__ float ws[8], ws2[8];
    if ((t & 31) == 0) { ws[t >> 5] = s; ws2[t >> 5] = s2; }
    __syncthreads();
    if (t < 32) {
        float a = (t < 8) ? ws[t] : 0.f;
        float b = (t < 8) ? ws2[t] : 0.f;
#pragma unroll
        for (int o = 4; o > 0; o >>= 1) {
            a += __shfl_xor_sync(0xffffffffu, a, o);
            b += __shfl_xor_sync(0xffffffffu, b, o);
        }
        if (t == 0) { ws[0] = a; ws2[0] = b; }
    }
    __syncthreads();
    const float mu  = ws[0] * (1.f / ED);
    const float var = ws2[0] * (1.f / ED) - mu * mu;
    const float inv = rsqrtf(var + 1e-5f);
    const int c = t * 4;
    float4 ga = *(const float4*)(gamma + c);
    float4 be = *(const float4*)(beta + c);
    float4 o4;
    o4.x = (v.x - mu) * inv * ga.x + be.x;
    o4.y = (v.y - mu) * inv * ga.y + be.y;
    o4.z = (v.z - mu) * inv * ga.z + be.z;
    o4.w = (v.w - mu) * inv * ga.w + be.w;
    *(float4*)(out + (size_t)row * ED + c) = o4;
}

// ---------------- launch ---------------------------------------------------------
extern "C" void kernel_launch(void* const* d_in, const int* in_sizes, int n_in,
                              void* d_out, int out_size)
{
    const float* x     = (const float*)d_in[0];
    const float* Wq    = (const float*)d_in[1];
    const float* bq    = (const float*)d_in[2];
    const float* Wk    = (const float*)d_in[3];
    const float* bk    = (const float*)d_in[4];
    const float* Wv    = (const float*)d_in[5];
    const float* bv    = (const float*)d_in[6];
    const float* M     = (const float*)d_in[7];
    const float* Wo    = (const float*)d_in[8];
    const float* bo    = (const float*)d_in[9];
    const float* gamma = (const float*)d_in[10];
    const float* beta  = (const float*)d_in[11];

    float* outp  = (float*)d_out;
    float* attnp = outp + (size_t)ROWS * ED;   // tuple order: out, then attn

    cudaFuncSetAttribute(scores_mma,
                         cudaFuncAttributeMaxDynamicSharedMemorySize, (int)SC_SMEM);
    cudaFuncSetAttribute(qm_mma,
                         cudaFuncAttributeMaxDynamicSharedMemorySize, (int)QM_SMEM);
    cudaFuncSetAttribute(attn_ctx_mma,
                         cudaFuncAttributeMaxDynamicSharedMemorySize, (int)AC_SMEM);

    dim3 gProj(ED / 128, ROWS / 128);            // (8, 32)
    dim3 gProjQK(ED / 128, ROWS / 128, 2);       // (8, 32, 2)

    prep_kernel<<<(N4X + 4 * N4W) / 256, 256>>>(x, Wq, Wk, Wv, Wo);   // idx 0
    hgemm_qk<<<gProjQK, 256>>>(bq, bk);                               // idx 1
    qm_mma<<<dim3(BHS / 128, 2), 256, QM_SMEM>>>(M);                  // idx 2
    scores_mma<<<dim3(SD / 256, BH), 256, SC_SMEM>>>();               // idx 3  <- profiled
    hgemm_v<<<gProj, 256>>>(bv);                                      // idx 4
    attn_ctx_mma<<<dim3(SD / 256, BH), 256, AC_SMEM>>>(attnp);        // idx 5
    hgemm_o<<<gProj, 256>>>(bo, x);                                   // idx 6
    ln_kernel<<<ROWS, 256>>>(gamma, beta, outp);                      // idx 7
}